// round 1
// baseline (speedup 1.0000x reference)
#include <cuda_runtime.h>
#include <math.h>

// ---------------- problem constants ----------------
constexpr int BATCH = 16;
constexpr int HH    = 16;
constexpr int WW    = 16;
constexpr int L     = 256;      // H*W
constexpr int DIM   = 768;
constexpr int NH    = 8;
constexpr int HD    = 96;
constexpr int NEXP  = 8;
constexpr int EB    = NEXP * BATCH;   // 128 (expert, batch) pairs
constexpr float SCALE = 0.102062072615966f; // 1/sqrt(96)

// ---------------- device scratch (static; no allocation) ----------------
__device__ float g_qkv [BATCH * L * 3 * DIM];     // (B,L,2304)
__device__ float g_ctx [BATCH * L * DIM];         // attention out (pre-proj)
__device__ float g_ctx2[BATCH * L * DIM];         // after sa_out proj
__device__ float g_q2  [BATCH * L * DIM];
__device__ float g_k2  [NEXP * DIM];
__device__ float g_aw  [BATCH * L * NEXP];
__device__ float g_wsel[EB];                      // gating weight per (e,b); 0 if unselected
__device__ float g_xz  [EB * L * 2 * DIM];        // expert in-proj
__device__ float g_xc  [EB * L * DIM];            // after depthwise conv + silu
__device__ float g_dbl [EB * 4 * L * 6];          // per-dir (dt_lin[4], B, C) projections
__device__ float g_y   [EB * L * DIM];            // summed scan outputs (spatial order)

// ---------------- helpers ----------------
__device__ __forceinline__ float siluf(float x) { return x / (1.f + __expf(-x)); }
__device__ __forceinline__ float softplusf(float x) {
    return (x > 20.f) ? x : log1pf(__expf(x));
}
// scan-time index -> spatial (row-major) index, per direction
__device__ __forceinline__ int dirmap(int dir, int t) {
    int tt = (dir & 1) ? (L - 1 - t) : t;
    if (dir < 2) return tt;
    return ((tt & 15) << 4) | (tt >> 4);   // vertical order: t = w*16+h -> l = h*16+w
}

// ---------------- generic 64x64 fp32 GEMM tile: C = A @ W^T + bias ----------------
// A: (rows,K) row-major, W: (cols,K) row-major. All dims multiples of 64/16.
__device__ __forceinline__ void gemm64(const float* __restrict__ A,
                                       const float* __restrict__ Wt,
                                       const float* __restrict__ bias,
                                       float* __restrict__ C,
                                       int K, int ldc) {
    __shared__ float As[16][65];
    __shared__ float Bs[16][65];
    const int tid = threadIdx.x;
    const int tx = tid & 15, ty = tid >> 4;
    float acc[4][4];
#pragma unroll
    for (int i = 0; i < 4; i++)
#pragma unroll
        for (int j = 0; j < 4; j++) acc[i][j] = 0.f;

    for (int k0 = 0; k0 < K; k0 += 16) {
#pragma unroll
        for (int i = 0; i < 4; i++) {
            As[tx][ty + i * 16] = A [(size_t)(ty + i * 16) * K + k0 + tx];
            Bs[tx][ty + i * 16] = Wt[(size_t)(ty + i * 16) * K + k0 + tx];
        }
        __syncthreads();
#pragma unroll
        for (int kk = 0; kk < 16; kk++) {
            float a[4], w[4];
#pragma unroll
            for (int i = 0; i < 4; i++) a[i] = As[kk][ty * 4 + i];
#pragma unroll
            for (int j = 0; j < 4; j++) w[j] = Bs[kk][tx * 4 + j];
#pragma unroll
            for (int i = 0; i < 4; i++)
#pragma unroll
                for (int j = 0; j < 4; j++) acc[i][j] += a[i] * w[j];
        }
        __syncthreads();
    }
#pragma unroll
    for (int i = 0; i < 4; i++)
#pragma unroll
        for (int j = 0; j < 4; j++)
            C[(size_t)(ty * 4 + i) * ldc + tx * 4 + j] = acc[i][j] + bias[tx * 4 + j];
}

__global__ void __launch_bounds__(256)
gemm_plain(const float* __restrict__ A, const float* __restrict__ Wt,
           const float* __restrict__ bias, float* __restrict__ C, int K, int N) {
    gemm64(A + (size_t)blockIdx.y * 64 * K,
           Wt + (size_t)blockIdx.x * 64 * K,
           bias + blockIdx.x * 64,
           C + (size_t)blockIdx.y * 64 * N + blockIdx.x * 64, K, N);
}

// expert in-proj GEMM, gated on selection
__global__ void __launch_bounds__(256)
gemm_xz_kernel(const float* __restrict__ x, const float* __restrict__ ew,
               const float* __restrict__ eb) {
    int z = blockIdx.z;
    if (g_wsel[z] == 0.f) return;
    int e = z >> 4, b = z & 15;
    gemm64(x + ((size_t)b * L + blockIdx.y * 64) * DIM,
           ew + ((size_t)e * 2 * DIM + blockIdx.x * 64) * DIM,
           eb + e * 2 * DIM + blockIdx.x * 64,
           g_xz + (size_t)z * L * 2 * DIM + (size_t)blockIdx.y * 64 * 2 * DIM + blockIdx.x * 64,
           DIM, 2 * DIM);
}

// ---------------- fused self-attention: one block per (b,h), K/V in smem ----------------
__global__ void __launch_bounds__(256) attn_kernel() {
    const int h = blockIdx.x, b = blockIdx.y;
    extern __shared__ float sm[];
    float* Ksh = sm;
    float* Vsh = sm + L * HD;
    const float* base = g_qkv + (size_t)b * L * 3 * DIM;
    const int tid = threadIdx.x;

    for (int i = tid; i < L * HD; i += 256) {
        int m = i / HD, d = i - m * HD;
        Ksh[i] = base[(size_t)m * 3 * DIM + DIM     + h * HD + d];
        Vsh[i] = base[(size_t)m * 3 * DIM + 2 * DIM + h * HD + d];
    }
    __syncthreads();

    float sc[L];
    {
        float rq[HD];
        const float* qp = base + (size_t)tid * 3 * DIM + h * HD;
#pragma unroll
        for (int d = 0; d < HD; d++) rq[d] = qp[d];
        float mx = -1e30f;
        for (int m = 0; m < L; m++) {
            float s = 0.f;
            const float* kp = Ksh + m * HD;
#pragma unroll
            for (int d = 0; d < HD; d++) s += rq[d] * kp[d];
            s *= SCALE;
            sc[m] = s;
            mx = fmaxf(mx, s);
        }
        float sum = 0.f;
        for (int m = 0; m < L; m++) { float e = __expf(sc[m] - mx); sc[m] = e; sum += e; }
        float inv = 1.f / sum;
        for (int m = 0; m < L; m++) sc[m] *= inv;
    }
    {
        float accv[HD];
#pragma unroll
        for (int d = 0; d < HD; d++) accv[d] = 0.f;
        for (int m = 0; m < L; m++) {
            float p = sc[m];
            const float* vp = Vsh + m * HD;
#pragma unroll
            for (int d = 0; d < HD; d++) accv[d] += p * vp[d];
        }
        float* op = g_ctx + ((size_t)b * L + tid) * DIM + h * HD;
#pragma unroll
        for (int d = 0; d < HD; d++) op[d] = accv[d];
    }
}

// ---------------- cross-attention gating ----------------
__global__ void k2_kernel(const float* __restrict__ eq, const float* __restrict__ ca_w,
                          const float* __restrict__ ca_b) {
    int e = blockIdx.x;
    for (int c = threadIdx.x; c < DIM; c += 256) {
        const float* w = ca_w + (size_t)(DIM + c) * DIM;
        const float* q = eq + e * DIM;
        float s = ca_b[DIM + c];
        for (int k = 0; k < DIM; k++) s += q[k] * w[k];
        g_k2[e * DIM + c] = s;
    }
}

__global__ void aw_kernel() {
    int bl = blockIdx.x;               // b*L + l
    int tid = threadIdx.x;             // 64 threads: (h,e)
    int h = tid >> 3, e = tid & 7;
    const float* q = g_q2 + (size_t)bl * DIM + h * HD;
    const float* k = g_k2 + e * DIM + h * HD;
    float s = 0.f;
    for (int d = 0; d < HD; d++) s += q[d] * k[d];
    s *= SCALE;
    float m = s;
#pragma unroll
    for (int o = 4; o; o >>= 1) m = fmaxf(m, __shfl_xor_sync(0xffffffffu, m, o, 8));
    float ex = __expf(s - m);
    float sum = ex;
#pragma unroll
    for (int o = 4; o; o >>= 1) sum += __shfl_xor_sync(0xffffffffu, sum, o, 8);
    float p = ex / sum;
    __shared__ float sh[64];
    sh[tid] = p;
    __syncthreads();
    if (tid < 8) {
        float a = 0.f;
        for (int hh = 0; hh < 8; hh++) a += sh[hh * 8 + tid];
        g_aw[(size_t)bl * 8 + tid] = a * 0.125f;
    }
}

__global__ void gate_kernel() {
    int b = blockIdx.x;
    __shared__ float s[8];
    if (threadIdx.x < 8) s[threadIdx.x] = 0.f;
    __syncthreads();
    const float* p = g_aw + ((size_t)b * L + threadIdx.x) * 8;
    for (int e = 0; e < 8; e++) atomicAdd(&s[e], p[e]);
    __syncthreads();
    if (threadIdx.x == 0) {
        float g[8];
        float mx = -1e30f;
        for (int e = 0; e < 8; e++) { g[e] = s[e] * (1.f / 256.f); mx = fmaxf(mx, g[e]); }
        float sum = 0.f;
        for (int e = 0; e < 8; e++) { g[e] = __expf(g[e] - mx); sum += g[e]; }
        for (int e = 0; e < 8; e++) g[e] /= sum;
        int i0 = 0;
        for (int e = 1; e < 8; e++) if (g[e] > g[i0]) i0 = e;
        int i1 = -1;
        for (int e = 0; e < 8; e++) if (e != i0 && (i1 < 0 || g[e] > g[i1])) i1 = e;
        float mm = fmaxf(g[i0], g[i1]);
        float e0 = __expf(g[i0] - mm), e1 = __expf(g[i1] - mm);
        for (int e = 0; e < 8; e++) g_wsel[e * BATCH + b] = 0.f;
        g_wsel[i0 * BATCH + b] = e0 / (e0 + e1);
        g_wsel[i1 * BATCH + b] = e1 / (e0 + e1);
    }
}

// ---------------- expert: depthwise conv 3x3 + bias + silu ----------------
__global__ void conv_kernel(const float* __restrict__ cw, const float* __restrict__ cb) {
    int z = blockIdx.y;
    if (g_wsel[z] == 0.f) return;
    int e = z >> 4;
    int pix = blockIdx.x;
    int py = pix >> 4, px = pix & 15;
    int c = threadIdx.x;
    const float* w = cw + ((size_t)e * DIM + c) * 9;
    const float* in = g_xz + (size_t)z * L * 2 * DIM;
    float acc = cb[e * DIM + c];
#pragma unroll
    for (int dy = -1; dy <= 1; dy++) {
        int y = py + dy;
        if ((unsigned)y >= 16u) continue;
#pragma unroll
        for (int dx = -1; dx <= 1; dx++) {
            int xw = px + dx;
            if ((unsigned)xw >= 16u) continue;
            acc += in[(size_t)(y * 16 + xw) * 2 * DIM + c] * w[(dy + 1) * 3 + (dx + 1)];
        }
    }
    g_xc[(size_t)z * L * DIM + (size_t)pix * DIM + c] = siluf(acc);
}

// ---------------- expert: per-direction (dt_lin,B,C) projections ----------------
__global__ void dbl_kernel(const float* __restrict__ xproj) {
    int z = blockIdx.y;
    if (g_wsel[z] == 0.f) return;
    int e = z >> 4;
    int dir = blockIdx.x;
    __shared__ float wsh[6 * DIM];
    const float* wp = xproj + (size_t)(e * 4 + dir) * 6 * DIM;
    for (int i = threadIdx.x; i < 6 * DIM; i += 256) wsh[i] = wp[i];
    __syncthreads();
    int warp = threadIdx.x >> 5, lane = threadIdx.x & 31;
    const float* xcb = g_xc + (size_t)z * L * DIM;
    for (int t = warp; t < L; t += 8) {
        int l = dirmap(dir, t);
        const float* row = xcb + (size_t)l * DIM;
        float a0 = 0, a1 = 0, a2 = 0, a3 = 0, a4 = 0, a5 = 0;
        for (int d = lane; d < DIM; d += 32) {
            float xv = row[d];
            a0 += xv * wsh[d];
            a1 += xv * wsh[DIM + d];
            a2 += xv * wsh[2 * DIM + d];
            a3 += xv * wsh[3 * DIM + d];
            a4 += xv * wsh[4 * DIM + d];
            a5 += xv * wsh[5 * DIM + d];
        }
#pragma unroll
        for (int o = 16; o; o >>= 1) {
            a0 += __shfl_xor_sync(0xffffffffu, a0, o);
            a1 += __shfl_xor_sync(0xffffffffu, a1, o);
            a2 += __shfl_xor_sync(0xffffffffu, a2, o);
            a3 += __shfl_xor_sync(0xffffffffu, a3, o);
            a4 += __shfl_xor_sync(0xffffffffu, a4, o);
            a5 += __shfl_xor_sync(0xffffffffu, a5, o);
        }
        if (lane == 0) {
            float* outp = g_dbl + ((size_t)(z * 4 + dir) * L + t) * 6;
            outp[0] = a0; outp[1] = a1; outp[2] = a2;
            outp[3] = a3; outp[4] = a4; outp[5] = a5;
        }
    }
}

// ---------------- expert: selective scan, 4 directions, accumulate spatially ----------------
__global__ void __launch_bounds__(192)
scan_kernel(const float* __restrict__ dtw, const float* __restrict__ dtb,
            const float* __restrict__ Alog, const float* __restrict__ Dp) {
    int z = blockIdx.y;
    if (g_wsel[z] == 0.f) return;
    int e = z >> 4;
    int d = blockIdx.x * 192 + threadIdx.x;
    __shared__ float dsh[L * 6];
    float yacc[L];
    for (int t = 0; t < L; t++) yacc[t] = 0.f;
    const float* xcb = g_xc + (size_t)z * L * DIM;

    for (int dir = 0; dir < 4; dir++) {
        __syncthreads();
        const float* db = g_dbl + (size_t)(z * 4 + dir) * L * 6;
        for (int i = threadIdx.x; i < L * 6; i += 192) dsh[i] = db[i];
        __syncthreads();
        int pb = (e * 4 + dir) * DIM + d;
        float w0 = dtw[(size_t)pb * 4 + 0], w1 = dtw[(size_t)pb * 4 + 1];
        float w2 = dtw[(size_t)pb * 4 + 2], w3 = dtw[(size_t)pb * 4 + 3];
        float bb = dtb[pb];
        float A  = -__expf(Alog[pb]);
        float Dv = Dp[pb];
        float hst = 0.f;
        for (int t = 0; t < L; t++) {
            const float* dr = dsh + t * 6;
            float dtl = dr[0] * w0 + dr[1] * w1 + dr[2] * w2 + dr[3] * w3 + bb;
            float dt = softplusf(dtl);
            int l = dirmap(dir, t);
            float xv = xcb[(size_t)l * DIM + d];
            hst = __expf(dt * A) * hst + (dt * xv) * dr[4];
            yacc[l] += hst * dr[5] + Dv * xv;
        }
    }
    float* yp = g_y + (size_t)z * L * DIM + d;
    for (int t = 0; t < L; t++) yp[(size_t)t * DIM] = yacc[t];
}

// ---------------- expert: LayerNorm * silu(z) gate, spatial mean, weighted combine ----------------
__global__ void __launch_bounds__(256)
finalize_kernel(const float* __restrict__ lns, const float* __restrict__ lnb,
                float* __restrict__ out) {
    int z = blockIdx.x;
    float wgt = g_wsel[z];
    if (wgt == 0.f) return;
    int e = z >> 4, b = z & 15;
    int tid = threadIdx.x;
    __shared__ float red[18];
    const float* yb = g_y + (size_t)z * L * DIM;
    const float* zb = g_xz + (size_t)z * L * 2 * DIM + DIM;
    float s0 = lns[e * DIM + tid], s1 = lns[e * DIM + tid + 256], s2 = lns[e * DIM + tid + 512];
    float b0 = lnb[e * DIM + tid], b1 = lnb[e * DIM + tid + 256], b2 = lnb[e * DIM + tid + 512];
    float a0 = 0.f, a1 = 0.f, a2 = 0.f;

    for (int l = 0; l < L; l++) {
        float y0 = yb[(size_t)l * DIM + tid];
        float y1 = yb[(size_t)l * DIM + tid + 256];
        float y2 = yb[(size_t)l * DIM + tid + 512];
        float s = y0 + y1 + y2;
        float ss = y0 * y0 + y1 * y1 + y2 * y2;
#pragma unroll
        for (int o = 16; o; o >>= 1) {
            s  += __shfl_xor_sync(0xffffffffu, s, o);
            ss += __shfl_xor_sync(0xffffffffu, ss, o);
        }
        int w = tid >> 5;
        if ((tid & 31) == 0) { red[w] = s; red[8 + w] = ss; }
        __syncthreads();
        if (tid == 0) {
            float S = 0.f, SS = 0.f;
            for (int i = 0; i < 8; i++) { S += red[i]; SS += red[8 + i]; }
            red[16] = S; red[17] = SS;
        }
        __syncthreads();
        float mu = red[16] * (1.f / 768.f);
        float var = red[17] * (1.f / 768.f) - mu * mu;
        float rstd = rsqrtf(var + 1e-5f);
        __syncthreads();

        float z0 = zb[(size_t)l * 2 * DIM + tid];
        float z1 = zb[(size_t)l * 2 * DIM + tid + 256];
        float z2 = zb[(size_t)l * 2 * DIM + tid + 512];
        a0 += ((y0 - mu) * rstd * s0 + b0) * siluf(z0);
        a1 += ((y1 - mu) * rstd * s1 + b1) * siluf(z1);
        a2 += ((y2 - mu) * rstd * s2 + b2) * siluf(z2);
    }
    float sc = wgt * (1.f / 256.f);
    atomicAdd(&out[b * DIM + tid],       a0 * sc);
    atomicAdd(&out[b * DIM + tid + 256], a1 * sc);
    atomicAdd(&out[b * DIM + tid + 512], a2 * sc);
}

__global__ void zero_kernel(float* __restrict__ out, int n) {
    int i = blockIdx.x * blockDim.x + threadIdx.x;
    if (i < n) out[i] = 0.f;
}

// ---------------- host launcher ----------------
extern "C" void kernel_launch(void* const* d_in, const int* in_sizes, int n_in,
                              void* d_out, int out_size) {
    const float* x         = (const float*)d_in[0];
    const float* sa_in_w   = (const float*)d_in[1];
    const float* sa_in_b   = (const float*)d_in[2];
    const float* sa_out_w  = (const float*)d_in[3];
    const float* sa_out_b  = (const float*)d_in[4];
    const float* ca_in_w   = (const float*)d_in[5];
    const float* ca_in_b   = (const float*)d_in[6];
    const float* eq        = (const float*)d_in[7];
    const float* e_in_w    = (const float*)d_in[8];
    const float* e_in_b    = (const float*)d_in[9];
    const float* e_conv_w  = (const float*)d_in[10];
    const float* e_conv_b  = (const float*)d_in[11];
    const float* e_xproj_w = (const float*)d_in[12];
    const float* e_dtw     = (const float*)d_in[13];
    const float* e_dtb     = (const float*)d_in[14];
    const float* e_Alog    = (const float*)d_in[15];
    const float* e_D       = (const float*)d_in[16];
    const float* e_lns     = (const float*)d_in[17];
    const float* e_lnb     = (const float*)d_in[18];
    float* out = (float*)d_out;

    float *qkv, *ctx, *ctx2, *q2;
    cudaGetSymbolAddress((void**)&qkv,  g_qkv);
    cudaGetSymbolAddress((void**)&ctx,  g_ctx);
    cudaGetSymbolAddress((void**)&ctx2, g_ctx2);
    cudaGetSymbolAddress((void**)&q2,   g_q2);

    cudaFuncSetAttribute(attn_kernel, cudaFuncAttributeMaxDynamicSharedMemorySize,
                         2 * L * HD * (int)sizeof(float));

    // attention + gating chain
    gemm_plain<<<dim3(3 * DIM / 64, BATCH * L / 64), 256>>>(x, sa_in_w, sa_in_b, qkv, DIM, 3 * DIM);
    attn_kernel<<<dim3(NH, BATCH), 256, 2 * L * HD * sizeof(float)>>>();
    gemm_plain<<<dim3(DIM / 64, BATCH * L / 64), 256>>>(ctx, sa_out_w, sa_out_b, ctx2, DIM, DIM);
    gemm_plain<<<dim3(DIM / 64, BATCH * L / 64), 256>>>(ctx2, ca_in_w, ca_in_b, q2, DIM, DIM);
    k2_kernel<<<NEXP, 256>>>(eq, ca_in_w, ca_in_b);
    aw_kernel<<<BATCH * L, 64>>>();
    gate_kernel<<<BATCH, 256>>>();

    // experts (gated per (e,b) on g_wsel)
    zero_kernel<<<(BATCH * DIM + 255) / 256, 256>>>(out, BATCH * DIM);
    gemm_xz_kernel<<<dim3(2 * DIM / 64, L / 64, EB), 256>>>(x, e_in_w, e_in_b);
    conv_kernel<<<dim3(L, EB), DIM>>>(e_conv_w, e_conv_b);
    dbl_kernel<<<dim3(4, EB), 256>>>(e_xproj_w);
    scan_kernel<<<dim3(4, EB), 192>>>(e_dtw, e_dtb, e_Alog, e_D);
    finalize_kernel<<<EB, 256>>>(e_lns, e_lnb, out);
}

// round 2
// speedup vs baseline: 1.3213x; 1.3213x over previous
#include <cuda_runtime.h>
#include <math.h>

// ---------------- problem constants ----------------
constexpr int BATCH = 16;
constexpr int L     = 256;      // H*W
constexpr int DIM   = 768;
constexpr int NH    = 8;
constexpr int HD    = 96;
constexpr int NEXP  = 8;
constexpr int EB    = NEXP * BATCH;   // 128 (expert, batch) pairs
constexpr float SCALE = 0.102062072615966f; // 1/sqrt(96)

// ---------------- device scratch (static; no allocation) ----------------
__device__ float g_qkv [BATCH * L * 3 * DIM];
__device__ float g_ctx [BATCH * L * DIM];
__device__ float g_ctx2[BATCH * L * DIM];
__device__ float g_q2  [BATCH * L * DIM];
__device__ float g_k2  [NEXP * DIM];
__device__ float g_aw  [BATCH * L * NEXP];
__device__ float g_wsel[EB];
__device__ float g_xz  [EB * L * 2 * DIM];
__device__ float g_xc  [EB * L * DIM];
__device__ float g_dbl [EB * 4 * L * 6];
__device__ float g_ydir[(size_t)EB * 4 * L * DIM];   // per-direction scan outputs (scan order)

// ---------------- helpers ----------------
__device__ __forceinline__ float siluf(float x) { return x / (1.f + __expf(-x)); }
__device__ __forceinline__ float softplusf(float x) {
    return (x > 20.f) ? x : log1pf(__expf(x));
}
__device__ __forceinline__ int dirmap(int dir, int t) {
    int tt = (dir & 1) ? (L - 1 - t) : t;
    if (dir < 2) return tt;
    return ((tt & 15) << 4) | (tt >> 4);
}

// ---------------- 128x128 fp32 GEMM tile, 8x8 per thread: C = A @ W^T + bias ----
// A: (M,K) row-major, W: (N,K) row-major. M,N multiples of 128, K of 16.
__device__ __forceinline__ void gemm128(const float* __restrict__ A,
                                        const float* __restrict__ Wt,
                                        const float* __restrict__ bias,
                                        float* __restrict__ C,
                                        int K, int ldc) {
    __shared__ float As[16][132];
    __shared__ float Bs[16][132];
    const int tid = threadIdx.x;
    const int tx = tid & 15, ty = tid >> 4;
    float acc[8][8];
#pragma unroll
    for (int i = 0; i < 8; i++)
#pragma unroll
        for (int j = 0; j < 8; j++) acc[i][j] = 0.f;

    for (int k0 = 0; k0 < K; k0 += 16) {
#pragma unroll
        for (int u = 0; u < 2; u++) {
            int t = tid + u * 256;
            int row = t >> 2, kc = (t & 3) << 2;
            float4 va = *(const float4*)&A [(size_t)row * K + k0 + kc];
            float4 vb = *(const float4*)&Wt[(size_t)row * K + k0 + kc];
            As[kc + 0][row] = va.x; As[kc + 1][row] = va.y;
            As[kc + 2][row] = va.z; As[kc + 3][row] = va.w;
            Bs[kc + 0][row] = vb.x; Bs[kc + 1][row] = vb.y;
            Bs[kc + 2][row] = vb.z; Bs[kc + 3][row] = vb.w;
        }
        __syncthreads();
#pragma unroll
        for (int k = 0; k < 16; k++) {
            float a[8], b[8];
            *(float4*)&a[0] = *(const float4*)&As[k][ty * 4];
            *(float4*)&a[4] = *(const float4*)&As[k][ty * 4 + 64];
            *(float4*)&b[0] = *(const float4*)&Bs[k][tx * 4];
            *(float4*)&b[4] = *(const float4*)&Bs[k][tx * 4 + 64];
#pragma unroll
            for (int i = 0; i < 8; i++)
#pragma unroll
                for (int j = 0; j < 8; j++) acc[i][j] += a[i] * b[j];
        }
        __syncthreads();
    }
#pragma unroll
    for (int i = 0; i < 8; i++) {
        int r = (i < 4) ? (ty * 4 + i) : (64 + ty * 4 + i - 4);
#pragma unroll
        for (int jb = 0; jb < 2; jb++) {
            int c0 = jb * 64 + tx * 4;
            float4 v;
            v.x = acc[i][jb * 4 + 0] + bias[c0 + 0];
            v.y = acc[i][jb * 4 + 1] + bias[c0 + 1];
            v.z = acc[i][jb * 4 + 2] + bias[c0 + 2];
            v.w = acc[i][jb * 4 + 3] + bias[c0 + 3];
            *(float4*)&C[(size_t)r * ldc + c0] = v;
        }
    }
}

__global__ void __launch_bounds__(256)
gemm_plain(const float* __restrict__ A, const float* __restrict__ Wt,
           const float* __restrict__ bias, float* __restrict__ C, int K, int N) {
    gemm128(A + (size_t)blockIdx.y * 128 * K,
            Wt + (size_t)blockIdx.x * 128 * K,
            bias + blockIdx.x * 128,
            C + (size_t)blockIdx.y * 128 * N + blockIdx.x * 128, K, N);
}

__global__ void __launch_bounds__(256)
gemm_xz_kernel(const float* __restrict__ x, const float* __restrict__ ew,
               const float* __restrict__ eb) {
    int z = blockIdx.z;
    if (g_wsel[z] == 0.f) return;
    int e = z >> 4, b = z & 15;
    gemm128(x + ((size_t)b * L + blockIdx.y * 128) * DIM,
            ew + ((size_t)e * 2 * DIM + blockIdx.x * 128) * DIM,
            eb + e * 2 * DIM + blockIdx.x * 128,
            g_xz + (size_t)z * L * 2 * DIM + (size_t)blockIdx.y * 128 * 2 * DIM + blockIdx.x * 128,
            DIM, 2 * DIM);
}

// ---------------- fused self-attention ----------------
__global__ void __launch_bounds__(256) attn_kernel() {
    const int h = blockIdx.x, b = blockIdx.y;
    extern __shared__ float sm[];
    float* Ksh = sm;
    float* Vsh = sm + L * HD;
    const float* base = g_qkv + (size_t)b * L * 3 * DIM;
    const int tid = threadIdx.x;

    for (int i = tid; i < L * HD; i += 256) {
        int m = i / HD, d = i - m * HD;
        Ksh[i] = base[(size_t)m * 3 * DIM + DIM     + h * HD + d];
        Vsh[i] = base[(size_t)m * 3 * DIM + 2 * DIM + h * HD + d];
    }
    __syncthreads();

    float sc[L];
    {
        float rq[HD];
        const float* qp = base + (size_t)tid * 3 * DIM + h * HD;
#pragma unroll
        for (int d = 0; d < HD; d++) rq[d] = qp[d];
        float mx = -1e30f;
        for (int m = 0; m < L; m++) {
            float s = 0.f;
            const float* kp = Ksh + m * HD;
#pragma unroll
            for (int d = 0; d < HD; d++) s += rq[d] * kp[d];
            s *= SCALE;
            sc[m] = s;
            mx = fmaxf(mx, s);
        }
        float sum = 0.f;
        for (int m = 0; m < L; m++) { float e = __expf(sc[m] - mx); sc[m] = e; sum += e; }
        float inv = 1.f / sum;
        for (int m = 0; m < L; m++) sc[m] *= inv;
    }
    {
        float accv[HD];
#pragma unroll
        for (int d = 0; d < HD; d++) accv[d] = 0.f;
        for (int m = 0; m < L; m++) {
            float p = sc[m];
            const float* vp = Vsh + m * HD;
#pragma unroll
            for (int d = 0; d < HD; d++) accv[d] += p * vp[d];
        }
        float* op = g_ctx + ((size_t)b * L + tid) * DIM + h * HD;
#pragma unroll
        for (int d = 0; d < HD; d++) op[d] = accv[d];
    }
}

// ---------------- cross-attention gating ----------------
__global__ void k2_kernel(const float* __restrict__ eq, const float* __restrict__ ca_w,
                          const float* __restrict__ ca_b) {
    int e = blockIdx.x;
    for (int c = threadIdx.x; c < DIM; c += 256) {
        const float* w = ca_w + (size_t)(DIM + c) * DIM;
        const float* q = eq + e * DIM;
        float s = ca_b[DIM + c];
        for (int k = 0; k < DIM; k++) s += q[k] * w[k];
        g_k2[e * DIM + c] = s;
    }
}

__global__ void aw_kernel() {
    int bl = blockIdx.x;
    int tid = threadIdx.x;
    int h = tid >> 3, e = tid & 7;
    const float* q = g_q2 + (size_t)bl * DIM + h * HD;
    const float* k = g_k2 + e * DIM + h * HD;
    float s = 0.f;
    for (int d = 0; d < HD; d++) s += q[d] * k[d];
    s *= SCALE;
    float m = s;
#pragma unroll
    for (int o = 4; o; o >>= 1) m = fmaxf(m, __shfl_xor_sync(0xffffffffu, m, o, 8));
    float ex = __expf(s - m);
    float sum = ex;
#pragma unroll
    for (int o = 4; o; o >>= 1) sum += __shfl_xor_sync(0xffffffffu, sum, o, 8);
    float p = ex / sum;
    __shared__ float sh[64];
    sh[tid] = p;
    __syncthreads();
    if (tid < 8) {
        float a = 0.f;
        for (int hh = 0; hh < 8; hh++) a += sh[hh * 8 + tid];
        g_aw[(size_t)bl * 8 + tid] = a * 0.125f;
    }
}

__global__ void gate_kernel() {
    int b = blockIdx.x;
    __shared__ float s[8];
    if (threadIdx.x < 8) s[threadIdx.x] = 0.f;
    __syncthreads();
    const float* p = g_aw + ((size_t)b * L + threadIdx.x) * 8;
    for (int e = 0; e < 8; e++) atomicAdd(&s[e], p[e]);
    __syncthreads();
    if (threadIdx.x == 0) {
        float g[8];
        float mx = -1e30f;
        for (int e = 0; e < 8; e++) { g[e] = s[e] * (1.f / 256.f); mx = fmaxf(mx, g[e]); }
        float sum = 0.f;
        for (int e = 0; e < 8; e++) { g[e] = __expf(g[e] - mx); sum += g[e]; }
        for (int e = 0; e < 8; e++) g[e] /= sum;
        int i0 = 0;
        for (int e = 1; e < 8; e++) if (g[e] > g[i0]) i0 = e;
        int i1 = -1;
        for (int e = 0; e < 8; e++) if (e != i0 && (i1 < 0 || g[e] > g[i1])) i1 = e;
        float mm = fmaxf(g[i0], g[i1]);
        float e0 = __expf(g[i0] - mm), e1 = __expf(g[i1] - mm);
        for (int e = 0; e < 8; e++) g_wsel[e * BATCH + b] = 0.f;
        g_wsel[i0 * BATCH + b] = e0 / (e0 + e1);
        g_wsel[i1 * BATCH + b] = e1 / (e0 + e1);
    }
}

// ---------------- expert: depthwise conv 3x3 + bias + silu ----------------
__global__ void conv_kernel(const float* __restrict__ cw, const float* __restrict__ cb) {
    int z = blockIdx.y;
    if (g_wsel[z] == 0.f) return;
    int e = z >> 4;
    int pix = blockIdx.x;
    int py = pix >> 4, px = pix & 15;
    int c = threadIdx.x;
    const float* w = cw + ((size_t)e * DIM + c) * 9;
    const float* in = g_xz + (size_t)z * L * 2 * DIM;
    float acc = cb[e * DIM + c];
#pragma unroll
    for (int dy = -1; dy <= 1; dy++) {
        int y = py + dy;
        if ((unsigned)y >= 16u) continue;
#pragma unroll
        for (int dx = -1; dx <= 1; dx++) {
            int xw = px + dx;
            if ((unsigned)xw >= 16u) continue;
            acc += in[(size_t)(y * 16 + xw) * 2 * DIM + c] * w[(dy + 1) * 3 + (dx + 1)];
        }
    }
    g_xc[(size_t)z * L * DIM + (size_t)pix * DIM + c] = siluf(acc);
}

// ---------------- expert: per-direction (dt_lin,B,C) projections ----------------
__global__ void dbl_kernel(const float* __restrict__ xproj) {
    int z = blockIdx.y;
    if (g_wsel[z] == 0.f) return;
    int e = z >> 4;
    int dir = blockIdx.x;
    __shared__ float wsh[6 * DIM];
    const float* wp = xproj + (size_t)(e * 4 + dir) * 6 * DIM;
    for (int i = threadIdx.x; i < 6 * DIM; i += 256) wsh[i] = wp[i];
    __syncthreads();
    int warp = threadIdx.x >> 5, lane = threadIdx.x & 31;
    const float* xcb = g_xc + (size_t)z * L * DIM;
    for (int t = warp; t < L; t += 8) {
        int l = dirmap(dir, t);
        const float* row = xcb + (size_t)l * DIM;
        float a0 = 0, a1 = 0, a2 = 0, a3 = 0, a4 = 0, a5 = 0;
        for (int d = lane; d < DIM; d += 32) {
            float xv = row[d];
            a0 += xv * wsh[d];
            a1 += xv * wsh[DIM + d];
            a2 += xv * wsh[2 * DIM + d];
            a3 += xv * wsh[3 * DIM + d];
            a4 += xv * wsh[4 * DIM + d];
            a5 += xv * wsh[5 * DIM + d];
        }
#pragma unroll
        for (int o = 16; o; o >>= 1) {
            a0 += __shfl_xor_sync(0xffffffffu, a0, o);
            a1 += __shfl_xor_sync(0xffffffffu, a1, o);
            a2 += __shfl_xor_sync(0xffffffffu, a2, o);
            a3 += __shfl_xor_sync(0xffffffffu, a3, o);
            a4 += __shfl_xor_sync(0xffffffffu, a4, o);
            a5 += __shfl_xor_sync(0xffffffffu, a5, o);
        }
        if (lane == 0) {
            float* outp = g_dbl + ((size_t)(z * 4 + dir) * L + t) * 6;
            outp[0] = a0; outp[1] = a1; outp[2] = a2;
            outp[3] = a3; outp[4] = a4; outp[5] = a5;
        }
    }
}

// ---------------- expert: selective scan (writes per-dir outputs, no local arrays) --
__global__ void __launch_bounds__(192)
scan_kernel(const float* __restrict__ dtw, const float* __restrict__ dtb,
            const float* __restrict__ Alog, const float* __restrict__ Dp) {
    int z = blockIdx.y;
    if (g_wsel[z] == 0.f) return;
    int e = z >> 4;
    int d = blockIdx.x * 192 + threadIdx.x;
    __shared__ float dsh[L * 6];
    const float* xcb = g_xc + (size_t)z * L * DIM;

    for (int dir = 0; dir < 4; dir++) {
        __syncthreads();
        const float* db = g_dbl + (size_t)(z * 4 + dir) * L * 6;
        for (int i = threadIdx.x; i < L * 6; i += 192) dsh[i] = db[i];
        __syncthreads();
        int pb = (e * 4 + dir) * DIM + d;
        float w0 = dtw[(size_t)pb * 4 + 0], w1 = dtw[(size_t)pb * 4 + 1];
        float w2 = dtw[(size_t)pb * 4 + 2], w3 = dtw[(size_t)pb * 4 + 3];
        float bb = dtb[pb];
        float A  = -__expf(Alog[pb]);
        float Dv = Dp[pb];
        float hst = 0.f;
        float* yp = g_ydir + (size_t)(z * 4 + dir) * L * DIM + d;
        for (int t = 0; t < L; t++) {
            const float* dr = dsh + t * 6;
            float dtl = dr[0] * w0 + dr[1] * w1 + dr[2] * w2 + dr[3] * w3 + bb;
            float dt = softplusf(dtl);
            int l = dirmap(dir, t);
            float xv = xcb[(size_t)l * DIM + d];
            hst = __expf(dt * A) * hst + (dt * xv) * dr[4];
            yp[(size_t)t * DIM] = hst * dr[5] + Dv * xv;
        }
    }
}

// ---------------- expert: gather dirs + LayerNorm + silu gate + mean + combine ------
__global__ void __launch_bounds__(256)
finalize_kernel(const float* __restrict__ lns, const float* __restrict__ lnb,
                float* __restrict__ out) {
    int z = blockIdx.x;
    float wgt = g_wsel[z];
    if (wgt == 0.f) return;
    int e = z >> 4, b = z & 15;
    int tid = threadIdx.x;
    __shared__ float red[18];
    const float* y0b = g_ydir + (size_t)(z * 4 + 0) * L * DIM;
    const float* y1b = g_ydir + (size_t)(z * 4 + 1) * L * DIM;
    const float* y2b = g_ydir + (size_t)(z * 4 + 2) * L * DIM;
    const float* y3b = g_ydir + (size_t)(z * 4 + 3) * L * DIM;
    const float* zb = g_xz + (size_t)z * L * 2 * DIM + DIM;
    float s0 = lns[e * DIM + tid], s1 = lns[e * DIM + tid + 256], s2 = lns[e * DIM + tid + 512];
    float b0 = lnb[e * DIM + tid], b1 = lnb[e * DIM + tid + 256], b2 = lnb[e * DIM + tid + 512];
    float a0 = 0.f, a1 = 0.f, a2 = 0.f;

    for (int l = 0; l < L; l++) {
        int lt = ((l & 15) << 4) | (l >> 4);
        size_t r0 = (size_t)l * DIM;
        size_t r1 = (size_t)(L - 1 - l) * DIM;
        size_t r2 = (size_t)lt * DIM;
        size_t r3 = (size_t)(L - 1 - lt) * DIM;
        float y0 = y0b[r0 + tid]       + y1b[r1 + tid]       + y2b[r2 + tid]       + y3b[r3 + tid];
        float y1 = y0b[r0 + tid + 256] + y1b[r1 + tid + 256] + y2b[r2 + tid + 256] + y3b[r3 + tid + 256];
        float y2 = y0b[r0 + tid + 512] + y1b[r1 + tid + 512] + y2b[r2 + tid + 512] + y3b[r3 + tid + 512];

        float s = y0 + y1 + y2;
        float ss = y0 * y0 + y1 * y1 + y2 * y2;
#pragma unroll
        for (int o = 16; o; o >>= 1) {
            s  += __shfl_xor_sync(0xffffffffu, s, o);
            ss += __shfl_xor_sync(0xffffffffu, ss, o);
        }
        int w = tid >> 5;
        if ((tid & 31) == 0) { red[w] = s; red[8 + w] = ss; }
        __syncthreads();
        if (tid == 0) {
            float S = 0.f, SS = 0.f;
            for (int i = 0; i < 8; i++) { S += red[i]; SS += red[8 + i]; }
            red[16] = S; red[17] = SS;
        }
        __syncthreads();
        float mu = red[16] * (1.f / 768.f);
        float var = red[17] * (1.f / 768.f) - mu * mu;
        float rstd = rsqrtf(var + 1e-5f);
        __syncthreads();

        float z0 = zb[(size_t)l * 2 * DIM + tid];
        float z1 = zb[(size_t)l * 2 * DIM + tid + 256];
        float z2 = zb[(size_t)l * 2 * DIM + tid + 512];
        a0 += ((y0 - mu) * rstd * s0 + b0) * siluf(z0);
        a1 += ((y1 - mu) * rstd * s1 + b1) * siluf(z1);
        a2 += ((y2 - mu) * rstd * s2 + b2) * siluf(z2);
    }
    float sc = wgt * (1.f / 256.f);
    atomicAdd(&out[b * DIM + tid],       a0 * sc);
    atomicAdd(&out[b * DIM + tid + 256], a1 * sc);
    atomicAdd(&out[b * DIM + tid + 512], a2 * sc);
}

__global__ void zero_kernel(float* __restrict__ out, int n) {
    int i = blockIdx.x * blockDim.x + threadIdx.x;
    if (i < n) out[i] = 0.f;
}

// ---------------- host launcher ----------------
extern "C" void kernel_launch(void* const* d_in, const int* in_sizes, int n_in,
                              void* d_out, int out_size) {
    const float* x         = (const float*)d_in[0];
    const float* sa_in_w   = (const float*)d_in[1];
    const float* sa_in_b   = (const float*)d_in[2];
    const float* sa_out_w  = (const float*)d_in[3];
    const float* sa_out_b  = (const float*)d_in[4];
    const float* ca_in_w   = (const float*)d_in[5];
    const float* ca_in_b   = (const float*)d_in[6];
    const float* eq        = (const float*)d_in[7];
    const float* e_in_w    = (const float*)d_in[8];
    const float* e_in_b    = (const float*)d_in[9];
    const float* e_conv_w  = (const float*)d_in[10];
    const float* e_conv_b  = (const float*)d_in[11];
    const float* e_xproj_w = (const float*)d_in[12];
    const float* e_dtw     = (const float*)d_in[13];
    const float* e_dtb     = (const float*)d_in[14];
    const float* e_Alog    = (const float*)d_in[15];
    const float* e_D       = (const float*)d_in[16];
    const float* e_lns     = (const float*)d_in[17];
    const float* e_lnb     = (const float*)d_in[18];
    float* out = (float*)d_out;

    float *qkv, *ctx, *ctx2, *q2;
    cudaGetSymbolAddress((void**)&qkv,  g_qkv);
    cudaGetSymbolAddress((void**)&ctx,  g_ctx);
    cudaGetSymbolAddress((void**)&ctx2, g_ctx2);
    cudaGetSymbolAddress((void**)&q2,   g_q2);

    cudaFuncSetAttribute(attn_kernel, cudaFuncAttributeMaxDynamicSharedMemorySize,
                         2 * L * HD * (int)sizeof(float));

    // attention + gating chain
    gemm_plain<<<dim3(3 * DIM / 128, BATCH * L / 128), 256>>>(x, sa_in_w, sa_in_b, qkv, DIM, 3 * DIM);
    attn_kernel<<<dim3(NH, BATCH), 256, 2 * L * HD * sizeof(float)>>>();
    gemm_plain<<<dim3(DIM / 128, BATCH * L / 128), 256>>>(ctx, sa_out_w, sa_out_b, ctx2, DIM, DIM);
    gemm_plain<<<dim3(DIM / 128, BATCH * L / 128), 256>>>(ctx2, ca_in_w, ca_in_b, q2, DIM, DIM);
    k2_kernel<<<NEXP, 256>>>(eq, ca_in_w, ca_in_b);
    aw_kernel<<<BATCH * L, 64>>>();
    gate_kernel<<<BATCH, 256>>>();

    // experts (gated per (e,b) on g_wsel)
    zero_kernel<<<(BATCH * DIM + 255) / 256, 256>>>(out, BATCH * DIM);
    gemm_xz_kernel<<<dim3(2 * DIM / 128, L / 128, EB), 256>>>(x, e_in_w, e_in_b);
    conv_kernel<<<dim3(L, EB), DIM>>>(e_conv_w, e_conv_b);
    dbl_kernel<<<dim3(4, EB), 256>>>(e_xproj_w);
    scan_kernel<<<dim3(4, EB), 192>>>(e_dtw, e_dtb, e_Alog, e_D);
    finalize_kernel<<<EB, 256>>>(e_lns, e_lnb, out);
}

// round 3
// speedup vs baseline: 1.3976x; 1.0578x over previous
#include <cuda_runtime.h>
#include <math.h>

// ---------------- problem constants ----------------
constexpr int BATCH = 16;
constexpr int L     = 256;      // H*W
constexpr int DIM   = 768;
constexpr int NH    = 8;
constexpr int HD    = 96;
constexpr int NEXP  = 8;
constexpr int EB    = NEXP * BATCH;   // 128 (expert, batch) pairs
constexpr float SCALE = 0.102062072615966f; // 1/sqrt(96)

// ---------------- device scratch (static; no allocation) ----------------
__device__ float g_qkv [BATCH * L * 3 * DIM];
__device__ float g_ctx [BATCH * L * DIM];
__device__ float g_ctx2[BATCH * L * DIM];
__device__ float g_q2  [BATCH * L * DIM];
__device__ float g_k2  [NEXP * DIM];
__device__ float g_aw  [BATCH * L * NEXP];
__device__ float g_wsel[EB];
__device__ float g_xz  [EB * L * 2 * DIM];
__device__ float g_xc  [EB * L * DIM];
__device__ float g_dbl [EB * 4 * L * 6];
__device__ float g_ydir[(size_t)EB * 4 * L * DIM];   // per-direction scan outputs (scan order)

// ---------------- helpers ----------------
__device__ __forceinline__ float siluf(float x) { return x / (1.f + __expf(-x)); }
__device__ __forceinline__ float softplusf(float x) {
    return (x > 20.f) ? x : log1pf(__expf(x));
}
__device__ __forceinline__ int dirmap(int dir, int t) {
    int tt = (dir & 1) ? (L - 1 - t) : t;
    if (dir < 2) return tt;
    return ((tt & 15) << 4) | (tt >> 4);
}

// ------- 128x128 fp32 GEMM tile, 8x8/thread, double-buffered smem -------
// A: (M,K) row-major, W: (N,K) row-major. M,N multiples of 128, K of 16.
__device__ __forceinline__ void gemm128(const float* __restrict__ A,
                                        const float* __restrict__ Wt,
                                        const float* __restrict__ bias,
                                        float* __restrict__ C,
                                        int K, int ldc) {
    __shared__ float As[2][16][132];
    __shared__ float Bs[2][16][132];
    const int tid = threadIdx.x;
    const int tx = tid & 15, ty = tid >> 4;
    // loader indices: thread handles rows r0,r1 (= tid/4, +64), k-cols kc..kc+3
    const int lrow0 = tid >> 2;
    const int lrow1 = lrow0 + 64;
    const int lkc   = (tid & 3) << 2;

    float acc[8][8];
#pragma unroll
    for (int i = 0; i < 8; i++)
#pragma unroll
        for (int j = 0; j < 8; j++) acc[i][j] = 0.f;

    float4 pa0, pa1, pb0, pb1;
    // prefetch k-block 0
    pa0 = *(const float4*)&A [(size_t)lrow0 * K + lkc];
    pa1 = *(const float4*)&A [(size_t)lrow1 * K + lkc];
    pb0 = *(const float4*)&Wt[(size_t)lrow0 * K + lkc];
    pb1 = *(const float4*)&Wt[(size_t)lrow1 * K + lkc];
    As[0][lkc + 0][lrow0] = pa0.x; As[0][lkc + 1][lrow0] = pa0.y;
    As[0][lkc + 2][lrow0] = pa0.z; As[0][lkc + 3][lrow0] = pa0.w;
    As[0][lkc + 0][lrow1] = pa1.x; As[0][lkc + 1][lrow1] = pa1.y;
    As[0][lkc + 2][lrow1] = pa1.z; As[0][lkc + 3][lrow1] = pa1.w;
    Bs[0][lkc + 0][lrow0] = pb0.x; Bs[0][lkc + 1][lrow0] = pb0.y;
    Bs[0][lkc + 2][lrow0] = pb0.z; Bs[0][lkc + 3][lrow0] = pb0.w;
    Bs[0][lkc + 0][lrow1] = pb1.x; Bs[0][lkc + 1][lrow1] = pb1.y;
    Bs[0][lkc + 2][lrow1] = pb1.z; Bs[0][lkc + 3][lrow1] = pb1.w;
    __syncthreads();

    int buf = 0;
    for (int k0 = 16; k0 < K; k0 += 16) {
        // issue loads for next k-block (latency overlapped with compute below)
        pa0 = *(const float4*)&A [(size_t)lrow0 * K + k0 + lkc];
        pa1 = *(const float4*)&A [(size_t)lrow1 * K + k0 + lkc];
        pb0 = *(const float4*)&Wt[(size_t)lrow0 * K + k0 + lkc];
        pb1 = *(const float4*)&Wt[(size_t)lrow1 * K + k0 + lkc];
#pragma unroll
        for (int k = 0; k < 16; k++) {
            float a[8], b[8];
            *(float4*)&a[0] = *(const float4*)&As[buf][k][ty * 4];
            *(float4*)&a[4] = *(const float4*)&As[buf][k][ty * 4 + 64];
            *(float4*)&b[0] = *(const float4*)&Bs[buf][k][tx * 4];
            *(float4*)&b[4] = *(const float4*)&Bs[buf][k][tx * 4 + 64];
#pragma unroll
            for (int i = 0; i < 8; i++)
#pragma unroll
                for (int j = 0; j < 8; j++) acc[i][j] += a[i] * b[j];
        }
        int nb = buf ^ 1;
        As[nb][lkc + 0][lrow0] = pa0.x; As[nb][lkc + 1][lrow0] = pa0.y;
        As[nb][lkc + 2][lrow0] = pa0.z; As[nb][lkc + 3][lrow0] = pa0.w;
        As[nb][lkc + 0][lrow1] = pa1.x; As[nb][lkc + 1][lrow1] = pa1.y;
        As[nb][lkc + 2][lrow1] = pa1.z; As[nb][lkc + 3][lrow1] = pa1.w;
        Bs[nb][lkc + 0][lrow0] = pb0.x; Bs[nb][lkc + 1][lrow0] = pb0.y;
        Bs[nb][lkc + 2][lrow0] = pb0.z; Bs[nb][lkc + 3][lrow0] = pb0.w;
        Bs[nb][lkc + 0][lrow1] = pb1.x; Bs[nb][lkc + 1][lrow1] = pb1.y;
        Bs[nb][lkc + 2][lrow1] = pb1.z; Bs[nb][lkc + 3][lrow1] = pb1.w;
        __syncthreads();
        buf = nb;
    }
    // last k-block
#pragma unroll
    for (int k = 0; k < 16; k++) {
        float a[8], b[8];
        *(float4*)&a[0] = *(const float4*)&As[buf][k][ty * 4];
        *(float4*)&a[4] = *(const float4*)&As[buf][k][ty * 4 + 64];
        *(float4*)&b[0] = *(const float4*)&Bs[buf][k][tx * 4];
        *(float4*)&b[4] = *(const float4*)&Bs[buf][k][tx * 4 + 64];
#pragma unroll
        for (int i = 0; i < 8; i++)
#pragma unroll
            for (int j = 0; j < 8; j++) acc[i][j] += a[i] * b[j];
    }

#pragma unroll
    for (int i = 0; i < 8; i++) {
        int r = (i < 4) ? (ty * 4 + i) : (64 + ty * 4 + i - 4);
#pragma unroll
        for (int jb = 0; jb < 2; jb++) {
            int c0 = jb * 64 + tx * 4;
            float4 v;
            v.x = acc[i][jb * 4 + 0] + bias[c0 + 0];
            v.y = acc[i][jb * 4 + 1] + bias[c0 + 1];
            v.z = acc[i][jb * 4 + 2] + bias[c0 + 2];
            v.w = acc[i][jb * 4 + 3] + bias[c0 + 3];
            *(float4*)&C[(size_t)r * ldc + c0] = v;
        }
    }
}

__global__ void __launch_bounds__(256, 2)
gemm_plain(const float* __restrict__ A, const float* __restrict__ Wt,
           const float* __restrict__ bias, float* __restrict__ C, int K, int N) {
    gemm128(A + (size_t)blockIdx.y * 128 * K,
            Wt + (size_t)blockIdx.x * 128 * K,
            bias + blockIdx.x * 128,
            C + (size_t)blockIdx.y * 128 * N + blockIdx.x * 128, K, N);
}

__global__ void __launch_bounds__(256, 2)
gemm_xz_kernel(const float* __restrict__ x, const float* __restrict__ ew,
               const float* __restrict__ eb) {
    int z = blockIdx.z;
    if (g_wsel[z] == 0.f) return;
    int e = z >> 4, b = z & 15;
    gemm128(x + ((size_t)b * L + blockIdx.y * 128) * DIM,
            ew + ((size_t)e * 2 * DIM + blockIdx.x * 128) * DIM,
            eb + e * 2 * DIM + blockIdx.x * 128,
            g_xz + (size_t)z * L * 2 * DIM + (size_t)blockIdx.y * 128 * 2 * DIM + blockIdx.x * 128,
            DIM, 2 * DIM);
}

// ---------------- fused self-attention ----------------
__global__ void __launch_bounds__(256) attn_kernel() {
    const int h = blockIdx.x, b = blockIdx.y;
    extern __shared__ float sm[];
    float* Ksh = sm;
    float* Vsh = sm + L * HD;
    const float* base = g_qkv + (size_t)b * L * 3 * DIM;
    const int tid = threadIdx.x;

    for (int i = tid; i < L * HD; i += 256) {
        int m = i / HD, d = i - m * HD;
        Ksh[i] = base[(size_t)m * 3 * DIM + DIM     + h * HD + d];
        Vsh[i] = base[(size_t)m * 3 * DIM + 2 * DIM + h * HD + d];
    }
    __syncthreads();

    float sc[L];
    {
        float rq[HD];
        const float* qp = base + (size_t)tid * 3 * DIM + h * HD;
#pragma unroll
        for (int d = 0; d < HD; d++) rq[d] = qp[d];
        float mx = -1e30f;
        for (int m = 0; m < L; m++) {
            float s = 0.f;
            const float* kp = Ksh + m * HD;
#pragma unroll
            for (int d = 0; d < HD; d++) s += rq[d] * kp[d];
            s *= SCALE;
            sc[m] = s;
            mx = fmaxf(mx, s);
        }
        float sum = 0.f;
        for (int m = 0; m < L; m++) { float e = __expf(sc[m] - mx); sc[m] = e; sum += e; }
        float inv = 1.f / sum;
        for (int m = 0; m < L; m++) sc[m] *= inv;
    }
    {
        float accv[HD];
#pragma unroll
        for (int d = 0; d < HD; d++) accv[d] = 0.f;
        for (int m = 0; m < L; m++) {
            float p = sc[m];
            const float* vp = Vsh + m * HD;
#pragma unroll
            for (int d = 0; d < HD; d++) accv[d] += p * vp[d];
        }
        float* op = g_ctx + ((size_t)b * L + tid) * DIM + h * HD;
#pragma unroll
        for (int d = 0; d < HD; d++) op[d] = accv[d];
    }
}

// ---------------- cross-attention gating ----------------
__global__ void k2_kernel(const float* __restrict__ eq, const float* __restrict__ ca_w,
                          const float* __restrict__ ca_b) {
    int e = blockIdx.x;
    for (int c = threadIdx.x; c < DIM; c += 256) {
        const float* w = ca_w + (size_t)(DIM + c) * DIM;
        const float* q = eq + e * DIM;
        float s = ca_b[DIM + c];
        for (int k = 0; k < DIM; k++) s += q[k] * w[k];
        g_k2[e * DIM + c] = s;
    }
}

__global__ void aw_kernel() {
    int bl = blockIdx.x;
    int tid = threadIdx.x;
    int h = tid >> 3, e = tid & 7;
    const float* q = g_q2 + (size_t)bl * DIM + h * HD;
    const float* k = g_k2 + e * DIM + h * HD;
    float s = 0.f;
    for (int d = 0; d < HD; d++) s += q[d] * k[d];
    s *= SCALE;
    float m = s;
#pragma unroll
    for (int o = 4; o; o >>= 1) m = fmaxf(m, __shfl_xor_sync(0xffffffffu, m, o, 8));
    float ex = __expf(s - m);
    float sum = ex;
#pragma unroll
    for (int o = 4; o; o >>= 1) sum += __shfl_xor_sync(0xffffffffu, sum, o, 8);
    float p = ex / sum;
    __shared__ float sh[64];
    sh[tid] = p;
    __syncthreads();
    if (tid < 8) {
        float a = 0.f;
        for (int hh = 0; hh < 8; hh++) a += sh[hh * 8 + tid];
        g_aw[(size_t)bl * 8 + tid] = a * 0.125f;
    }
}

__global__ void gate_kernel() {
    int b = blockIdx.x;
    __shared__ float s[8];
    if (threadIdx.x < 8) s[threadIdx.x] = 0.f;
    __syncthreads();
    const float* p = g_aw + ((size_t)b * L + threadIdx.x) * 8;
    for (int e = 0; e < 8; e++) atomicAdd(&s[e], p[e]);
    __syncthreads();
    if (threadIdx.x == 0) {
        float g[8];
        float mx = -1e30f;
        for (int e = 0; e < 8; e++) { g[e] = s[e] * (1.f / 256.f); mx = fmaxf(mx, g[e]); }
        float sum = 0.f;
        for (int e = 0; e < 8; e++) { g[e] = __expf(g[e] - mx); sum += g[e]; }
        for (int e = 0; e < 8; e++) g[e] /= sum;
        int i0 = 0;
        for (int e = 1; e < 8; e++) if (g[e] > g[i0]) i0 = e;
        int i1 = -1;
        for (int e = 0; e < 8; e++) if (e != i0 && (i1 < 0 || g[e] > g[i1])) i1 = e;
        float mm = fmaxf(g[i0], g[i1]);
        float e0 = __expf(g[i0] - mm), e1 = __expf(g[i1] - mm);
        for (int e = 0; e < 8; e++) g_wsel[e * BATCH + b] = 0.f;
        g_wsel[i0 * BATCH + b] = e0 / (e0 + e1);
        g_wsel[i1 * BATCH + b] = e1 / (e0 + e1);
    }
}

// ---------------- expert: depthwise conv 3x3 + bias + silu ----------------
__global__ void conv_kernel(const float* __restrict__ cw, const float* __restrict__ cb) {
    int z = blockIdx.y;
    if (g_wsel[z] == 0.f) return;
    int e = z >> 4;
    int pix = blockIdx.x;
    int py = pix >> 4, px = pix & 15;
    int c = threadIdx.x;
    const float* w = cw + ((size_t)e * DIM + c) * 9;
    const float* in = g_xz + (size_t)z * L * 2 * DIM;
    float acc = cb[e * DIM + c];
#pragma unroll
    for (int dy = -1; dy <= 1; dy++) {
        int y = py + dy;
        if ((unsigned)y >= 16u) continue;
#pragma unroll
        for (int dx = -1; dx <= 1; dx++) {
            int xw = px + dx;
            if ((unsigned)xw >= 16u) continue;
            acc += in[(size_t)(y * 16 + xw) * 2 * DIM + c] * w[(dy + 1) * 3 + (dx + 1)];
        }
    }
    g_xc[(size_t)z * L * DIM + (size_t)pix * DIM + c] = siluf(acc);
}

// ---------------- expert: per-direction (dt_lin,B,C) projections ----------------
__global__ void dbl_kernel(const float* __restrict__ xproj) {
    int z = blockIdx.y;
    if (g_wsel[z] == 0.f) return;
    int e = z >> 4;
    int dir = blockIdx.x;
    __shared__ float wsh[6 * DIM];
    const float* wp = xproj + (size_t)(e * 4 + dir) * 6 * DIM;
    for (int i = threadIdx.x; i < 6 * DIM; i += 256) wsh[i] = wp[i];
    __syncthreads();
    int warp = threadIdx.x >> 5, lane = threadIdx.x & 31;
    const float* xcb = g_xc + (size_t)z * L * DIM;
    for (int t = warp; t < L; t += 8) {
        int l = dirmap(dir, t);
        const float* row = xcb + (size_t)l * DIM;
        float a0 = 0, a1 = 0, a2 = 0, a3 = 0, a4 = 0, a5 = 0;
        for (int d = lane; d < DIM; d += 32) {
            float xv = row[d];
            a0 += xv * wsh[d];
            a1 += xv * wsh[DIM + d];
            a2 += xv * wsh[2 * DIM + d];
            a3 += xv * wsh[3 * DIM + d];
            a4 += xv * wsh[4 * DIM + d];
            a5 += xv * wsh[5 * DIM + d];
        }
#pragma unroll
        for (int o = 16; o; o >>= 1) {
            a0 += __shfl_xor_sync(0xffffffffu, a0, o);
            a1 += __shfl_xor_sync(0xffffffffu, a1, o);
            a2 += __shfl_xor_sync(0xffffffffu, a2, o);
            a3 += __shfl_xor_sync(0xffffffffu, a3, o);
            a4 += __shfl_xor_sync(0xffffffffu, a4, o);
            a5 += __shfl_xor_sync(0xffffffffu, a5, o);
        }
        if (lane == 0) {
            float* outp = g_dbl + ((size_t)(z * 4 + dir) * L + t) * 6;
            outp[0] = a0; outp[1] = a1; outp[2] = a2;
            outp[3] = a3; outp[4] = a4; outp[5] = a5;
        }
    }
}

// ---------------- expert: selective scan ----------------
__global__ void __launch_bounds__(192)
scan_kernel(const float* __restrict__ dtw, const float* __restrict__ dtb,
            const float* __restrict__ Alog, const float* __restrict__ Dp) {
    int z = blockIdx.y;
    if (g_wsel[z] == 0.f) return;
    int e = z >> 4;
    int d = blockIdx.x * 192 + threadIdx.x;
    __shared__ float dsh[L * 6];
    const float* xcb = g_xc + (size_t)z * L * DIM;

    for (int dir = 0; dir < 4; dir++) {
        __syncthreads();
        const float* db = g_dbl + (size_t)(z * 4 + dir) * L * 6;
        for (int i = threadIdx.x; i < L * 6; i += 192) dsh[i] = db[i];
        __syncthreads();
        int pb = (e * 4 + dir) * DIM + d;
        float w0 = dtw[(size_t)pb * 4 + 0], w1 = dtw[(size_t)pb * 4 + 1];
        float w2 = dtw[(size_t)pb * 4 + 2], w3 = dtw[(size_t)pb * 4 + 3];
        float bb = dtb[pb];
        float A  = -__expf(Alog[pb]);
        float Dv = Dp[pb];
        float hst = 0.f;
        float* yp = g_ydir + (size_t)(z * 4 + dir) * L * DIM + d;
        for (int t = 0; t < L; t++) {
            const float* dr = dsh + t * 6;
            float dtl = dr[0] * w0 + dr[1] * w1 + dr[2] * w2 + dr[3] * w3 + bb;
            float dt = softplusf(dtl);
            int l = dirmap(dir, t);
            float xv = xcb[(size_t)l * DIM + d];
            hst = __expf(dt * A) * hst + (dt * xv) * dr[4];
            yp[(size_t)t * DIM] = hst * dr[5] + Dv * xv;
        }
    }
}

// ------- expert finalize: two-phase LN (no per-row block barriers) -------
__global__ void __launch_bounds__(256)
finalize_kernel(const float* __restrict__ lns, const float* __restrict__ lnb,
                float* __restrict__ out) {
    int z = blockIdx.x;
    float wgt = g_wsel[z];
    if (wgt == 0.f) return;
    int e = z >> 4, b = z & 15;
    int tid = threadIdx.x;
    int wid = tid >> 5, lane = tid & 31;
    __shared__ float smu[L], srs[L];

    const float* y0b = g_ydir + (size_t)(z * 4 + 0) * L * DIM;
    const float* y1b = g_ydir + (size_t)(z * 4 + 1) * L * DIM;
    const float* y2b = g_ydir + (size_t)(z * 4 + 2) * L * DIM;
    const float* y3b = g_ydir + (size_t)(z * 4 + 3) * L * DIM;
    const float* zb = g_xz + (size_t)z * L * 2 * DIM + DIM;

    // phase 1: per-row mean / rstd, one warp per row
    for (int l = wid; l < L; l += 8) {
        int lt = ((l & 15) << 4) | (l >> 4);
        const float* p0 = y0b + (size_t)l * DIM;
        const float* p1 = y1b + (size_t)(L - 1 - l) * DIM;
        const float* p2 = y2b + (size_t)lt * DIM;
        const float* p3 = y3b + (size_t)(L - 1 - lt) * DIM;
        float s = 0.f, ss = 0.f;
        for (int d = lane; d < DIM; d += 32) {
            float v = p0[d] + p1[d] + p2[d] + p3[d];
            s += v; ss += v * v;
        }
#pragma unroll
        for (int o = 16; o; o >>= 1) {
            s  += __shfl_xor_sync(0xffffffffu, s, o);
            ss += __shfl_xor_sync(0xffffffffu, ss, o);
        }
        if (lane == 0) {
            float mu = s * (1.f / 768.f);
            float var = ss * (1.f / 768.f) - mu * mu;
            smu[l] = mu;
            srs[l] = rsqrtf(var + 1e-5f);
        }
    }
    __syncthreads();

    // phase 2: normalize, gate, accumulate spatial mean
    float s0 = lns[e * DIM + tid], s1 = lns[e * DIM + tid + 256], s2 = lns[e * DIM + tid + 512];
    float b0 = lnb[e * DIM + tid], b1 = lnb[e * DIM + tid + 256], b2 = lnb[e * DIM + tid + 512];
    float a0 = 0.f, a1 = 0.f, a2 = 0.f;

    for (int l = 0; l < L; l++) {
        int lt = ((l & 15) << 4) | (l >> 4);
        size_t r0 = (size_t)l * DIM;
        size_t r1 = (size_t)(L - 1 - l) * DIM;
        size_t r2 = (size_t)lt * DIM;
        size_t r3 = (size_t)(L - 1 - lt) * DIM;
        float y0 = y0b[r0 + tid]       + y1b[r1 + tid]       + y2b[r2 + tid]       + y3b[r3 + tid];
        float y1 = y0b[r0 + tid + 256] + y1b[r1 + tid + 256] + y2b[r2 + tid + 256] + y3b[r3 + tid + 256];
        float y2 = y0b[r0 + tid + 512] + y1b[r1 + tid + 512] + y2b[r2 + tid + 512] + y3b[r3 + tid + 512];
        float mu = smu[l], rstd = srs[l];

        float z0 = zb[(size_t)l * 2 * DIM + tid];
        float z1 = zb[(size_t)l * 2 * DIM + tid + 256];
        float z2 = zb[(size_t)l * 2 * DIM + tid + 512];
        a0 += ((y0 - mu) * rstd * s0 + b0) * siluf(z0);
        a1 += ((y1 - mu) * rstd * s1 + b1) * siluf(z1);
        a2 += ((y2 - mu) * rstd * s2 + b2) * siluf(z2);
    }
    float sc = wgt * (1.f / 256.f);
    atomicAdd(&out[b * DIM + tid],       a0 * sc);
    atomicAdd(&out[b * DIM + tid + 256], a1 * sc);
    atomicAdd(&out[b * DIM + tid + 512], a2 * sc);
}

__global__ void zero_kernel(float* __restrict__ out, int n) {
    int i = blockIdx.x * blockDim.x + threadIdx.x;
    if (i < n) out[i] = 0.f;
}

// ---------------- host launcher ----------------
extern "C" void kernel_launch(void* const* d_in, const int* in_sizes, int n_in,
                              void* d_out, int out_size) {
    const float* x         = (const float*)d_in[0];
    const float* sa_in_w   = (const float*)d_in[1];
    const float* sa_in_b   = (const float*)d_in[2];
    const float* sa_out_w  = (const float*)d_in[3];
    const float* sa_out_b  = (const float*)d_in[4];
    const float* ca_in_w   = (const float*)d_in[5];
    const float* ca_in_b   = (const float*)d_in[6];
    const float* eq        = (const float*)d_in[7];
    const float* e_in_w    = (const float*)d_in[8];
    const float* e_in_b    = (const float*)d_in[9];
    const float* e_conv_w  = (const float*)d_in[10];
    const float* e_conv_b  = (const float*)d_in[11];
    const float* e_xproj_w = (const float*)d_in[12];
    const float* e_dtw     = (const float*)d_in[13];
    const float* e_dtb     = (const float*)d_in[14];
    const float* e_Alog    = (const float*)d_in[15];
    const float* e_D       = (const float*)d_in[16];
    const float* e_lns     = (const float*)d_in[17];
    const float* e_lnb     = (const float*)d_in[18];
    float* out = (float*)d_out;

    float *qkv, *ctx, *ctx2, *q2;
    cudaGetSymbolAddress((void**)&qkv,  g_qkv);
    cudaGetSymbolAddress((void**)&ctx,  g_ctx);
    cudaGetSymbolAddress((void**)&ctx2, g_ctx2);
    cudaGetSymbolAddress((void**)&q2,   g_q2);

    cudaFuncSetAttribute(attn_kernel, cudaFuncAttributeMaxDynamicSharedMemorySize,
                         2 * L * HD * (int)sizeof(float));

    // attention + gating chain
    gemm_plain<<<dim3(3 * DIM / 128, BATCH * L / 128), 256>>>(x, sa_in_w, sa_in_b, qkv, DIM, 3 * DIM);
    attn_kernel<<<dim3(NH, BATCH), 256, 2 * L * HD * sizeof(float)>>>();
    gemm_plain<<<dim3(DIM / 128, BATCH * L / 128), 256>>>(ctx, sa_out_w, sa_out_b, ctx2, DIM, DIM);
    gemm_plain<<<dim3(DIM / 128, BATCH * L / 128), 256>>>(ctx2, ca_in_w, ca_in_b, q2, DIM, DIM);
    k2_kernel<<<NEXP, 256>>>(eq, ca_in_w, ca_in_b);
    aw_kernel<<<BATCH * L, 64>>>();
    gate_kernel<<<BATCH, 256>>>();

    // experts (gated per (e,b) on g_wsel)
    zero_kernel<<<(BATCH * DIM + 255) / 256, 256>>>(out, BATCH * DIM);
    gemm_xz_kernel<<<dim3(2 * DIM / 128, L / 128, EB), 256>>>(x, e_in_w, e_in_b);
    conv_kernel<<<dim3(L, EB), DIM>>>(e_conv_w, e_conv_b);
    dbl_kernel<<<dim3(4, EB), 256>>>(e_xproj_w);
    scan_kernel<<<dim3(4, EB), 192>>>(e_dtw, e_dtb, e_Alog, e_D);
    finalize_kernel<<<EB, 256>>>(e_lns, e_lnb, out);
}

// round 4
// speedup vs baseline: 1.6642x; 1.1908x over previous
#include <cuda_runtime.h>
#include <math.h>
#include <stdint.h>

// ---------------- problem constants ----------------
constexpr int BATCH = 16;
constexpr int L     = 256;      // H*W
constexpr int DIM   = 768;
constexpr int NH    = 8;
constexpr int HD    = 96;
constexpr int NEXP  = 8;
constexpr int EB    = NEXP * BATCH;   // 128 (expert, batch) pairs
constexpr float SCALE = 0.102062072615966f; // 1/sqrt(96)

// ---------------- device scratch (static; no allocation) ----------------
__device__ float g_qkv   [BATCH * L * 3 * DIM];
__device__ float g_ctx   [BATCH * L * DIM];
__device__ float g_k2    [NEXP * DIM];
__device__ float g_qvec  [64 * DIM];              // fused gating projection vectors (he = h*8+e)
__device__ float g_const [64];
__device__ float g_scores[BATCH * L * 64];
__device__ float g_aw    [BATCH * L * NEXP];
__device__ float g_wsel  [EB];
__device__ float g_xz    [EB * L * 2 * DIM];
__device__ float g_xc    [EB * L * DIM];
__device__ float g_dbl   [EB * 4 * L * 6];
__device__ float g_ydir  [(size_t)EB * 4 * L * DIM];

// ---------------- helpers ----------------
__device__ __forceinline__ float siluf(float x) { return x / (1.f + __expf(-x)); }
__device__ __forceinline__ float softplusf(float x) {
    return (x > 20.f) ? x : log1pf(__expf(x));
}
__device__ __forceinline__ int dirmap(int dir, int t) {
    int tt = (dir & 1) ? (L - 1 - t) : t;
    if (dir < 2) return tt;
    return ((tt & 15) << 4) | (tt >> 4);
}
__device__ __forceinline__ uint32_t f2tf32(float f) {
    uint32_t u;
    asm("cvt.rna.tf32.f32 %0, %1;" : "=r"(u) : "f"(f));
    return u;
}
__device__ __forceinline__ void mma_tf32(float* c, uint32_t a0, uint32_t a1,
                                         uint32_t a2, uint32_t a3,
                                         uint32_t b0, uint32_t b1) {
    asm volatile(
        "mma.sync.aligned.m16n8k8.row.col.f32.tf32.tf32.f32 "
        "{%0,%1,%2,%3}, {%4,%5,%6,%7}, {%8,%9}, {%0,%1,%2,%3};"
        : "+f"(c[0]), "+f"(c[1]), "+f"(c[2]), "+f"(c[3])
        : "r"(a0), "r"(a1), "r"(a2), "r"(a3), "r"(b0), "r"(b1));
}

// ------- 128x128 fp32 GEMM tile, 8x8/thread, double-buffered smem -------
__device__ __forceinline__ void gemm128(const float* __restrict__ A,
                                        const float* __restrict__ Wt,
                                        const float* __restrict__ bias,
                                        float* __restrict__ C,
                                        int K, int ldc) {
    __shared__ float As[2][16][132];
    __shared__ float Bs[2][16][132];
    const int tid = threadIdx.x;
    const int tx = tid & 15, ty = tid >> 4;
    const int lrow0 = tid >> 2;
    const int lrow1 = lrow0 + 64;
    const int lkc   = (tid & 3) << 2;

    float acc[8][8];
#pragma unroll
    for (int i = 0; i < 8; i++)
#pragma unroll
        for (int j = 0; j < 8; j++) acc[i][j] = 0.f;

    float4 pa0, pa1, pb0, pb1;
    pa0 = *(const float4*)&A [(size_t)lrow0 * K + lkc];
    pa1 = *(const float4*)&A [(size_t)lrow1 * K + lkc];
    pb0 = *(const float4*)&Wt[(size_t)lrow0 * K + lkc];
    pb1 = *(const float4*)&Wt[(size_t)lrow1 * K + lkc];
    As[0][lkc + 0][lrow0] = pa0.x; As[0][lkc + 1][lrow0] = pa0.y;
    As[0][lkc + 2][lrow0] = pa0.z; As[0][lkc + 3][lrow0] = pa0.w;
    As[0][lkc + 0][lrow1] = pa1.x; As[0][lkc + 1][lrow1] = pa1.y;
    As[0][lkc + 2][lrow1] = pa1.z; As[0][lkc + 3][lrow1] = pa1.w;
    Bs[0][lkc + 0][lrow0] = pb0.x; Bs[0][lkc + 1][lrow0] = pb0.y;
    Bs[0][lkc + 2][lrow0] = pb0.z; Bs[0][lkc + 3][lrow0] = pb0.w;
    Bs[0][lkc + 0][lrow1] = pb1.x; Bs[0][lkc + 1][lrow1] = pb1.y;
    Bs[0][lkc + 2][lrow1] = pb1.z; Bs[0][lkc + 3][lrow1] = pb1.w;
    __syncthreads();

    int buf = 0;
    for (int k0 = 16; k0 < K; k0 += 16) {
        pa0 = *(const float4*)&A [(size_t)lrow0 * K + k0 + lkc];
        pa1 = *(const float4*)&A [(size_t)lrow1 * K + k0 + lkc];
        pb0 = *(const float4*)&Wt[(size_t)lrow0 * K + k0 + lkc];
        pb1 = *(const float4*)&Wt[(size_t)lrow1 * K + k0 + lkc];
#pragma unroll
        for (int k = 0; k < 16; k++) {
            float a[8], b[8];
            *(float4*)&a[0] = *(const float4*)&As[buf][k][ty * 4];
            *(float4*)&a[4] = *(const float4*)&As[buf][k][ty * 4 + 64];
            *(float4*)&b[0] = *(const float4*)&Bs[buf][k][tx * 4];
            *(float4*)&b[4] = *(const float4*)&Bs[buf][k][tx * 4 + 64];
#pragma unroll
            for (int i = 0; i < 8; i++)
#pragma unroll
                for (int j = 0; j < 8; j++) acc[i][j] += a[i] * b[j];
        }
        int nb = buf ^ 1;
        As[nb][lkc + 0][lrow0] = pa0.x; As[nb][lkc + 1][lrow0] = pa0.y;
        As[nb][lkc + 2][lrow0] = pa0.z; As[nb][lkc + 3][lrow0] = pa0.w;
        As[nb][lkc + 0][lrow1] = pa1.x; As[nb][lkc + 1][lrow1] = pa1.y;
        As[nb][lkc + 2][lrow1] = pa1.z; As[nb][lkc + 3][lrow1] = pa1.w;
        Bs[nb][lkc + 0][lrow0] = pb0.x; Bs[nb][lkc + 1][lrow0] = pb0.y;
        Bs[nb][lkc + 2][lrow0] = pb0.z; Bs[nb][lkc + 3][lrow0] = pb0.w;
        Bs[nb][lkc + 0][lrow1] = pb1.x; Bs[nb][lkc + 1][lrow1] = pb1.y;
        Bs[nb][lkc + 2][lrow1] = pb1.z; Bs[nb][lkc + 3][lrow1] = pb1.w;
        __syncthreads();
        buf = nb;
    }
#pragma unroll
    for (int k = 0; k < 16; k++) {
        float a[8], b[8];
        *(float4*)&a[0] = *(const float4*)&As[buf][k][ty * 4];
        *(float4*)&a[4] = *(const float4*)&As[buf][k][ty * 4 + 64];
        *(float4*)&b[0] = *(const float4*)&Bs[buf][k][tx * 4];
        *(float4*)&b[4] = *(const float4*)&Bs[buf][k][tx * 4 + 64];
#pragma unroll
        for (int i = 0; i < 8; i++)
#pragma unroll
            for (int j = 0; j < 8; j++) acc[i][j] += a[i] * b[j];
    }

#pragma unroll
    for (int i = 0; i < 8; i++) {
        int r = (i < 4) ? (ty * 4 + i) : (64 + ty * 4 + i - 4);
#pragma unroll
        for (int jb = 0; jb < 2; jb++) {
            int c0 = jb * 64 + tx * 4;
            float4 v;
            v.x = acc[i][jb * 4 + 0] + bias[c0 + 0];
            v.y = acc[i][jb * 4 + 1] + bias[c0 + 1];
            v.z = acc[i][jb * 4 + 2] + bias[c0 + 2];
            v.w = acc[i][jb * 4 + 3] + bias[c0 + 3];
            *(float4*)&C[(size_t)r * ldc + c0] = v;
        }
    }
}

__global__ void __launch_bounds__(256, 2)
gemm_plain(const float* __restrict__ A, const float* __restrict__ Wt,
           const float* __restrict__ bias, float* __restrict__ C, int K, int N) {
    gemm128(A + (size_t)blockIdx.y * 128 * K,
            Wt + (size_t)blockIdx.x * 128 * K,
            bias + blockIdx.x * 128,
            C + (size_t)blockIdx.y * 128 * N + blockIdx.x * 128, K, N);
}

// ------- tf32 tensor-core GEMM for the gated expert in-proj -------
// Block 128x128, 8 warps (2 m-halves x 4 n-quarters), mma.m16n8k8.
__global__ void __launch_bounds__(256, 2)
gemm_xz_tf32(const float* __restrict__ x, const float* __restrict__ ew,
             const float* __restrict__ eb) {
    int z = blockIdx.z;
    if (g_wsel[z] == 0.f) return;
    int e = z >> 4, b = z & 15;
    const float* A  = x  + ((size_t)b * L + blockIdx.y * 128) * DIM;
    const float* Wt = ew + ((size_t)e * 2 * DIM + blockIdx.x * 128) * DIM;
    const float* bias = eb + e * 2 * DIM + blockIdx.x * 128;
    float* C = g_xz + (size_t)z * L * 2 * DIM
             + (size_t)blockIdx.y * 128 * 2 * DIM + blockIdx.x * 128;

    // smem layout [row][k] with pitch 20 words -> conflict-free frag loads
    __shared__ uint32_t As[2][128][20];
    __shared__ uint32_t Bs[2][128][20];

    const int tid  = threadIdx.x;
    const int wid  = tid >> 5, lane = tid & 31;
    const int mw   = wid & 1, nw = wid >> 1;
    const int m0   = mw * 64, n0 = nw * 32;
    const int r    = lane >> 2, c4 = lane & 3;
    const int lrow0 = tid >> 2;          // 0..63
    const int lrow1 = lrow0 + 64;
    const int lkc   = (tid & 3) << 2;    // 0,4,8,12

    float acc[4][4][4];
#pragma unroll
    for (int i = 0; i < 4; i++)
#pragma unroll
        for (int j = 0; j < 4; j++)
#pragma unroll
            for (int q = 0; q < 4; q++) acc[i][j][q] = 0.f;

    float4 pa0, pa1, pb0, pb1;
    pa0 = *(const float4*)&A [(size_t)lrow0 * DIM + lkc];
    pa1 = *(const float4*)&A [(size_t)lrow1 * DIM + lkc];
    pb0 = *(const float4*)&Wt[(size_t)lrow0 * DIM + lkc];
    pb1 = *(const float4*)&Wt[(size_t)lrow1 * DIM + lkc];
    As[0][lrow0][lkc + 0] = f2tf32(pa0.x); As[0][lrow0][lkc + 1] = f2tf32(pa0.y);
    As[0][lrow0][lkc + 2] = f2tf32(pa0.z); As[0][lrow0][lkc + 3] = f2tf32(pa0.w);
    As[0][lrow1][lkc + 0] = f2tf32(pa1.x); As[0][lrow1][lkc + 1] = f2tf32(pa1.y);
    As[0][lrow1][lkc + 2] = f2tf32(pa1.z); As[0][lrow1][lkc + 3] = f2tf32(pa1.w);
    Bs[0][lrow0][lkc + 0] = f2tf32(pb0.x); Bs[0][lrow0][lkc + 1] = f2tf32(pb0.y);
    Bs[0][lrow0][lkc + 2] = f2tf32(pb0.z); Bs[0][lrow0][lkc + 3] = f2tf32(pb0.w);
    Bs[0][lrow1][lkc + 0] = f2tf32(pb1.x); Bs[0][lrow1][lkc + 1] = f2tf32(pb1.y);
    Bs[0][lrow1][lkc + 2] = f2tf32(pb1.z); Bs[0][lrow1][lkc + 3] = f2tf32(pb1.w);
    __syncthreads();

    int buf = 0;
    for (int k0 = 16; k0 <= DIM; k0 += 16) {
        if (k0 < DIM) {
            pa0 = *(const float4*)&A [(size_t)lrow0 * DIM + k0 + lkc];
            pa1 = *(const float4*)&A [(size_t)lrow1 * DIM + k0 + lkc];
            pb0 = *(const float4*)&Wt[(size_t)lrow0 * DIM + k0 + lkc];
            pb1 = *(const float4*)&Wt[(size_t)lrow1 * DIM + k0 + lkc];
        }
#pragma unroll
        for (int kk = 0; kk < 16; kk += 8) {
            uint32_t bf0[4], bf1[4];
#pragma unroll
            for (int fn = 0; fn < 4; fn++) {
                bf0[fn] = Bs[buf][n0 + fn * 8 + r][kk + c4];
                bf1[fn] = Bs[buf][n0 + fn * 8 + r][kk + 4 + c4];
            }
#pragma unroll
            for (int fm = 0; fm < 4; fm++) {
                uint32_t a0 = As[buf][m0 + fm * 16 + r    ][kk + c4];
                uint32_t a1 = As[buf][m0 + fm * 16 + r + 8][kk + c4];
                uint32_t a2 = As[buf][m0 + fm * 16 + r    ][kk + 4 + c4];
                uint32_t a3 = As[buf][m0 + fm * 16 + r + 8][kk + 4 + c4];
#pragma unroll
                for (int fn = 0; fn < 4; fn++)
                    mma_tf32(acc[fm][fn], a0, a1, a2, a3, bf0[fn], bf1[fn]);
            }
        }
        if (k0 < DIM) {
            int nb = buf ^ 1;
            As[nb][lrow0][lkc + 0] = f2tf32(pa0.x); As[nb][lrow0][lkc + 1] = f2tf32(pa0.y);
            As[nb][lrow0][lkc + 2] = f2tf32(pa0.z); As[nb][lrow0][lkc + 3] = f2tf32(pa0.w);
            As[nb][lrow1][lkc + 0] = f2tf32(pa1.x); As[nb][lrow1][lkc + 1] = f2tf32(pa1.y);
            As[nb][lrow1][lkc + 2] = f2tf32(pa1.z); As[nb][lrow1][lkc + 3] = f2tf32(pa1.w);
            Bs[nb][lrow0][lkc + 0] = f2tf32(pb0.x); Bs[nb][lrow0][lkc + 1] = f2tf32(pb0.y);
            Bs[nb][lrow0][lkc + 2] = f2tf32(pb0.z); Bs[nb][lrow0][lkc + 3] = f2tf32(pb0.w);
            Bs[nb][lrow1][lkc + 0] = f2tf32(pb1.x); Bs[nb][lrow1][lkc + 1] = f2tf32(pb1.y);
            Bs[nb][lrow1][lkc + 2] = f2tf32(pb1.z); Bs[nb][lrow1][lkc + 3] = f2tf32(pb1.w);
            __syncthreads();
            buf = nb;
        }
    }

#pragma unroll
    for (int fm = 0; fm < 4; fm++) {
#pragma unroll
        for (int fn = 0; fn < 4; fn++) {
            int rl = m0 + fm * 16 + r;
            int cl = n0 + fn * 8 + (lane & 3) * 2;
            float2 v0, v1;
            v0.x = acc[fm][fn][0] + bias[cl];
            v0.y = acc[fm][fn][1] + bias[cl + 1];
            v1.x = acc[fm][fn][2] + bias[cl];
            v1.y = acc[fm][fn][3] + bias[cl + 1];
            *(float2*)&C[(size_t)rl * 2 * DIM + cl]       = v0;
            *(float2*)&C[(size_t)(rl + 8) * 2 * DIM + cl] = v1;
        }
    }
}

// ---------------- fused self-attention ----------------
__global__ void __launch_bounds__(256) attn_kernel() {
    const int h = blockIdx.x, b = blockIdx.y;
    extern __shared__ float sm[];
    float* Ksh = sm;
    float* Vsh = sm + L * HD;
    const float* base = g_qkv + (size_t)b * L * 3 * DIM;
    const int tid = threadIdx.x;

    for (int i = tid; i < L * HD; i += 256) {
        int m = i / HD, d = i - m * HD;
        Ksh[i] = base[(size_t)m * 3 * DIM + DIM     + h * HD + d];
        Vsh[i] = base[(size_t)m * 3 * DIM + 2 * DIM + h * HD + d];
    }
    __syncthreads();

    float sc[L];
    {
        float rq[HD];
        const float* qp = base + (size_t)tid * 3 * DIM + h * HD;
#pragma unroll
        for (int d = 0; d < HD; d++) rq[d] = qp[d];
        float mx = -1e30f;
        for (int m = 0; m < L; m++) {
            float s = 0.f;
            const float* kp = Ksh + m * HD;
#pragma unroll
            for (int d = 0; d < HD; d++) s += rq[d] * kp[d];
            s *= SCALE;
            sc[m] = s;
            mx = fmaxf(mx, s);
        }
        float sum = 0.f;
        for (int m = 0; m < L; m++) { float e = __expf(sc[m] - mx); sc[m] = e; sum += e; }
        float inv = 1.f / sum;
        for (int m = 0; m < L; m++) sc[m] *= inv;
    }
    {
        float accv[HD];
#pragma unroll
        for (int d = 0; d < HD; d++) accv[d] = 0.f;
        for (int m = 0; m < L; m++) {
            float p = sc[m];
            const float* vp = Vsh + m * HD;
#pragma unroll
            for (int d = 0; d < HD; d++) accv[d] += p * vp[d];
        }
        float* op = g_ctx + ((size_t)b * L + tid) * DIM + h * HD;
#pragma unroll
        for (int d = 0; d < HD; d++) op[d] = accv[d];
    }
}

// ---------------- fused gating projection ----------------
__global__ void k2_kernel(const float* __restrict__ eq, const float* __restrict__ ca_w,
                          const float* __restrict__ ca_b) {
    int e = blockIdx.x;
    for (int c = threadIdx.x; c < DIM; c += 256) {
        const float* w = ca_w + (size_t)(DIM + c) * DIM;
        const float* q = eq + e * DIM;
        float s = ca_b[DIM + c];
        for (int k = 0; k < DIM; k++) s += q[k] * w[k];
        g_k2[e * DIM + c] = s;
    }
}

// Qvec[he] = Wo^T (Wq_h^T k2[e,h]);  const[he] = bo.(Wq_h^T k2) + bq_h.k2
__global__ void __launch_bounds__(256)
vq_kernel(const float* __restrict__ ca_w, const float* __restrict__ ca_b,
          const float* __restrict__ sa_ow, const float* __restrict__ sa_ob) {
    int he = blockIdx.x;
    int e = he & 7, h = he >> 3;
    int tid = threadIdx.x;
    __shared__ float k2s[HD];
    __shared__ float v[DIM];
    __shared__ float red[256];

    if (tid < HD) k2s[tid] = g_k2[e * DIM + h * HD + tid];
    __syncthreads();

    for (int c = tid; c < DIM; c += 256) {
        float s = 0.f;
        for (int d = 0; d < HD; d++) s += ca_w[(size_t)(h * HD + d) * DIM + c] * k2s[d];
        v[c] = s;
    }
    __syncthreads();

    float part = 0.f;
    for (int c = tid; c < DIM; c += 256) part += sa_ob[c] * v[c];
    red[tid] = part;
    __syncthreads();
    for (int s = 128; s; s >>= 1) {
        if (tid < s) red[tid] += red[tid + s];
        __syncthreads();
    }
    if (tid == 0) {
        float c1 = 0.f;
        for (int d = 0; d < HD; d++) c1 += ca_b[h * HD + d] * k2s[d];
        g_const[he] = red[0] + c1;
    }

    for (int m = tid; m < DIM; m += 256) {
        float s = 0.f;
        for (int c = 0; c < DIM; c++) s += v[c] * sa_ow[(size_t)c * DIM + m];
        g_qvec[(size_t)he * DIM + m] = s;
    }
}

// scores[bl, he] = ctx[bl] . Qvec[he]   (64 tokens x 64 he per block)
__global__ void __launch_bounds__(256)
scores_kernel() {
    __shared__ float As[16][68];
    __shared__ float Qs[16][68];
    const int tid = threadIdx.x;
    const int tx = tid & 15, ty = tid >> 4;
    const int row = tid >> 2, kc = (tid & 3) << 2;
    const float* A = g_ctx + (size_t)blockIdx.x * 64 * DIM;

    float acc[4][4];
#pragma unroll
    for (int i = 0; i < 4; i++)
#pragma unroll
        for (int j = 0; j < 4; j++) acc[i][j] = 0.f;

    for (int k0 = 0; k0 < DIM; k0 += 16) {
        float4 va = *(const float4*)&A[(size_t)row * DIM + k0 + kc];
        float4 vq = *(const float4*)&g_qvec[(size_t)row * DIM + k0 + kc];
        As[kc + 0][row] = va.x; As[kc + 1][row] = va.y;
        As[kc + 2][row] = va.z; As[kc + 3][row] = va.w;
        Qs[kc + 0][row] = vq.x; Qs[kc + 1][row] = vq.y;
        Qs[kc + 2][row] = vq.z; Qs[kc + 3][row] = vq.w;
        __syncthreads();
#pragma unroll
        for (int k = 0; k < 16; k++) {
            float a[4], q[4];
            *(float4*)&a[0] = *(const float4*)&As[k][ty * 4];
            *(float4*)&q[0] = *(const float4*)&Qs[k][tx * 4];
#pragma unroll
            for (int i = 0; i < 4; i++)
#pragma unroll
                for (int j = 0; j < 4; j++) acc[i][j] += a[i] * q[j];
        }
        __syncthreads();
    }
#pragma unroll
    for (int i = 0; i < 4; i++)
#pragma unroll
        for (int j = 0; j < 4; j++)
            g_scores[((size_t)blockIdx.x * 64 + ty * 4 + i) * 64 + tx * 4 + j] = acc[i][j];
}

__global__ void aw_kernel() {
    int bl = blockIdx.x;
    int tid = threadIdx.x;        // he = h*8+e
    float s = (g_scores[(size_t)bl * 64 + tid] + g_const[tid]) * SCALE;
    float m = s;
#pragma unroll
    for (int o = 4; o; o >>= 1) m = fmaxf(m, __shfl_xor_sync(0xffffffffu, m, o, 8));
    float ex = __expf(s - m);
    float sum = ex;
#pragma unroll
    for (int o = 4; o; o >>= 1) sum += __shfl_xor_sync(0xffffffffu, sum, o, 8);
    float p = ex / sum;
    __shared__ float sh[64];
    sh[tid] = p;
    __syncthreads();
    if (tid < 8) {
        float a = 0.f;
        for (int hh = 0; hh < 8; hh++) a += sh[hh * 8 + tid];
        g_aw[(size_t)bl * 8 + tid] = a * 0.125f;
    }
}

__global__ void gate_kernel() {
    int b = blockIdx.x;
    __shared__ float s[8];
    if (threadIdx.x < 8) s[threadIdx.x] = 0.f;
    __syncthreads();
    const float* p = g_aw + ((size_t)b * L + threadIdx.x) * 8;
    for (int e = 0; e < 8; e++) atomicAdd(&s[e], p[e]);
    __syncthreads();
    if (threadIdx.x == 0) {
        float g[8];
        float mx = -1e30f;
        for (int e = 0; e < 8; e++) { g[e] = s[e] * (1.f / 256.f); mx = fmaxf(mx, g[e]); }
        float sum = 0.f;
        for (int e = 0; e < 8; e++) { g[e] = __expf(g[e] - mx); sum += g[e]; }
        for (int e = 0; e < 8; e++) g[e] /= sum;
        int i0 = 0;
        for (int e = 1; e < 8; e++) if (g[e] > g[i0]) i0 = e;
        int i1 = -1;
        for (int e = 0; e < 8; e++) if (e != i0 && (i1 < 0 || g[e] > g[i1])) i1 = e;
        float mm = fmaxf(g[i0], g[i1]);
        float e0 = __expf(g[i0] - mm), e1 = __expf(g[i1] - mm);
        for (int e = 0; e < 8; e++) g_wsel[e * BATCH + b] = 0.f;
        g_wsel[i0 * BATCH + b] = e0 / (e0 + e1);
        g_wsel[i1 * BATCH + b] = e1 / (e0 + e1);
    }
}

// ---------------- expert: depthwise conv 3x3 + bias + silu ----------------
__global__ void conv_kernel(const float* __restrict__ cw, const float* __restrict__ cb) {
    int z = blockIdx.y;
    if (g_wsel[z] == 0.f) return;
    int e = z >> 4;
    int pix = blockIdx.x;
    int py = pix >> 4, px = pix & 15;
    int c = threadIdx.x;
    const float* w = cw + ((size_t)e * DIM + c) * 9;
    const float* in = g_xz + (size_t)z * L * 2 * DIM;
    float acc = cb[e * DIM + c];
#pragma unroll
    for (int dy = -1; dy <= 1; dy++) {
        int y = py + dy;
        if ((unsigned)y >= 16u) continue;
#pragma unroll
        for (int dx = -1; dx <= 1; dx++) {
            int xw = px + dx;
            if ((unsigned)xw >= 16u) continue;
            acc += in[(size_t)(y * 16 + xw) * 2 * DIM + c] * w[(dy + 1) * 3 + (dx + 1)];
        }
    }
    g_xc[(size_t)z * L * DIM + (size_t)pix * DIM + c] = siluf(acc);
}

// ---------------- expert: per-direction (dt_lin,B,C) projections ----------------
__global__ void dbl_kernel(const float* __restrict__ xproj) {
    int z = blockIdx.y;
    if (g_wsel[z] == 0.f) return;
    int e = z >> 4;
    int dir = blockIdx.x;
    __shared__ float wsh[6 * DIM];
    const float* wp = xproj + (size_t)(e * 4 + dir) * 6 * DIM;
    for (int i = threadIdx.x; i < 6 * DIM; i += 256) wsh[i] = wp[i];
    __syncthreads();
    int warp = threadIdx.x >> 5, lane = threadIdx.x & 31;
    const float* xcb = g_xc + (size_t)z * L * DIM;
    for (int t = warp; t < L; t += 8) {
        int l = dirmap(dir, t);
        const float* row = xcb + (size_t)l * DIM;
        float a0 = 0, a1 = 0, a2 = 0, a3 = 0, a4 = 0, a5 = 0;
        for (int d = lane; d < DIM; d += 32) {
            float xv = row[d];
            a0 += xv * wsh[d];
            a1 += xv * wsh[DIM + d];
            a2 += xv * wsh[2 * DIM + d];
            a3 += xv * wsh[3 * DIM + d];
            a4 += xv * wsh[4 * DIM + d];
            a5 += xv * wsh[5 * DIM + d];
        }
#pragma unroll
        for (int o = 16; o; o >>= 1) {
            a0 += __shfl_xor_sync(0xffffffffu, a0, o);
            a1 += __shfl_xor_sync(0xffffffffu, a1, o);
            a2 += __shfl_xor_sync(0xffffffffu, a2, o);
            a3 += __shfl_xor_sync(0xffffffffu, a3, o);
            a4 += __shfl_xor_sync(0xffffffffu, a4, o);
            a5 += __shfl_xor_sync(0xffffffffu, a5, o);
        }
        if (lane == 0) {
            float* outp = g_dbl + ((size_t)(z * 4 + dir) * L + t) * 6;
            outp[0] = a0; outp[1] = a1; outp[2] = a2;
            outp[3] = a3; outp[4] = a4; outp[5] = a5;
        }
    }
}

// ---------------- expert: selective scan ----------------
__global__ void __launch_bounds__(192)
scan_kernel(const float* __restrict__ dtw, const float* __restrict__ dtb,
            const float* __restrict__ Alog, const float* __restrict__ Dp) {
    int z = blockIdx.y;
    if (g_wsel[z] == 0.f) return;
    int e = z >> 4;
    int d = blockIdx.x * 192 + threadIdx.x;
    __shared__ float dsh[L * 6];
    const float* xcb = g_xc + (size_t)z * L * DIM;

    for (int dir = 0; dir < 4; dir++) {
        __syncthreads();
        const float* db = g_dbl + (size_t)(z * 4 + dir) * L * 6;
        for (int i = threadIdx.x; i < L * 6; i += 192) dsh[i] = db[i];
        __syncthreads();
        int pb = (e * 4 + dir) * DIM + d;
        float w0 = dtw[(size_t)pb * 4 + 0], w1 = dtw[(size_t)pb * 4 + 1];
        float w2 = dtw[(size_t)pb * 4 + 2], w3 = dtw[(size_t)pb * 4 + 3];
        float bb = dtb[pb];
        float A  = -__expf(Alog[pb]);
        float Dv = Dp[pb];
        float hst = 0.f;
        float* yp = g_ydir + (size_t)(z * 4 + dir) * L * DIM + d;
        for (int t = 0; t < L; t++) {
            const float* dr = dsh + t * 6;
            float dtl = dr[0] * w0 + dr[1] * w1 + dr[2] * w2 + dr[3] * w3 + bb;
            float dt = softplusf(dtl);
            int l = dirmap(dir, t);
            float xv = xcb[(size_t)l * DIM + d];
            hst = __expf(dt * A) * hst + (dt * xv) * dr[4];
            yp[(size_t)t * DIM] = hst * dr[5] + Dv * xv;
        }
    }
}

// ------- expert finalize: two-phase LN -------
__global__ void __launch_bounds__(256)
finalize_kernel(const float* __restrict__ lns, const float* __restrict__ lnb,
                float* __restrict__ out) {
    int z = blockIdx.x;
    float wgt = g_wsel[z];
    if (wgt == 0.f) return;
    int e = z >> 4, b = z & 15;
    int tid = threadIdx.x;
    int wid = tid >> 5, lane = tid & 31;
    __shared__ float smu[L], srs[L];

    const float* y0b = g_ydir + (size_t)(z * 4 + 0) * L * DIM;
    const float* y1b = g_ydir + (size_t)(z * 4 + 1) * L * DIM;
    const float* y2b = g_ydir + (size_t)(z * 4 + 2) * L * DIM;
    const float* y3b = g_ydir + (size_t)(z * 4 + 3) * L * DIM;
    const float* zb = g_xz + (size_t)z * L * 2 * DIM + DIM;

    for (int l = wid; l < L; l += 8) {
        int lt = ((l & 15) << 4) | (l >> 4);
        const float* p0 = y0b + (size_t)l * DIM;
        const float* p1 = y1b + (size_t)(L - 1 - l) * DIM;
        const float* p2 = y2b + (size_t)lt * DIM;
        const float* p3 = y3b + (size_t)(L - 1 - lt) * DIM;
        float s = 0.f, ss = 0.f;
        for (int d = lane; d < DIM; d += 32) {
            float v = p0[d] + p1[d] + p2[d] + p3[d];
            s += v; ss += v * v;
        }
#pragma unroll
        for (int o = 16; o; o >>= 1) {
            s  += __shfl_xor_sync(0xffffffffu, s, o);
            ss += __shfl_xor_sync(0xffffffffu, ss, o);
        }
        if (lane == 0) {
            float mu = s * (1.f / 768.f);
            float var = ss * (1.f / 768.f) - mu * mu;
            smu[l] = mu;
            srs[l] = rsqrtf(var + 1e-5f);
        }
    }
    __syncthreads();

    float s0 = lns[e * DIM + tid], s1 = lns[e * DIM + tid + 256], s2 = lns[e * DIM + tid + 512];
    float b0 = lnb[e * DIM + tid], b1 = lnb[e * DIM + tid + 256], b2 = lnb[e * DIM + tid + 512];
    float a0 = 0.f, a1 = 0.f, a2 = 0.f;

    for (int l = 0; l < L; l++) {
        int lt = ((l & 15) << 4) | (l >> 4);
        size_t r0 = (size_t)l * DIM;
        size_t r1 = (size_t)(L - 1 - l) * DIM;
        size_t r2 = (size_t)lt * DIM;
        size_t r3 = (size_t)(L - 1 - lt) * DIM;
        float y0 = y0b[r0 + tid]       + y1b[r1 + tid]       + y2b[r2 + tid]       + y3b[r3 + tid];
        float y1 = y0b[r0 + tid + 256] + y1b[r1 + tid + 256] + y2b[r2 + tid + 256] + y3b[r3 + tid + 256];
        float y2 = y0b[r0 + tid + 512] + y1b[r1 + tid + 512] + y2b[r2 + tid + 512] + y3b[r3 + tid + 512];
        float mu = smu[l], rstd = srs[l];

        float z0 = zb[(size_t)l * 2 * DIM + tid];
        float z1 = zb[(size_t)l * 2 * DIM + tid + 256];
        float z2 = zb[(size_t)l * 2 * DIM + tid + 512];
        a0 += ((y0 - mu) * rstd * s0 + b0) * siluf(z0);
        a1 += ((y1 - mu) * rstd * s1 + b1) * siluf(z1);
        a2 += ((y2 - mu) * rstd * s2 + b2) * siluf(z2);
    }
    float sc = wgt * (1.f / 256.f);
    atomicAdd(&out[b * DIM + tid],       a0 * sc);
    atomicAdd(&out[b * DIM + tid + 256], a1 * sc);
    atomicAdd(&out[b * DIM + tid + 512], a2 * sc);
}

__global__ void zero_kernel(float* __restrict__ out, int n) {
    int i = blockIdx.x * blockDim.x + threadIdx.x;
    if (i < n) out[i] = 0.f;
}

// ---------------- host launcher ----------------
extern "C" void kernel_launch(void* const* d_in, const int* in_sizes, int n_in,
                              void* d_out, int out_size) {
    const float* x         = (const float*)d_in[0];
    const float* sa_in_w   = (const float*)d_in[1];
    const float* sa_in_b   = (const float*)d_in[2];
    const float* sa_out_w  = (const float*)d_in[3];
    const float* sa_out_b  = (const float*)d_in[4];
    const float* ca_in_w   = (const float*)d_in[5];
    const float* ca_in_b   = (const float*)d_in[6];
    const float* eq        = (const float*)d_in[7];
    const float* e_in_w    = (const float*)d_in[8];
    const float* e_in_b    = (const float*)d_in[9];
    const float* e_conv_w  = (const float*)d_in[10];
    const float* e_conv_b  = (const float*)d_in[11];
    const float* e_xproj_w = (const float*)d_in[12];
    const float* e_dtw     = (const float*)d_in[13];
    const float* e_dtb     = (const float*)d_in[14];
    const float* e_Alog    = (const float*)d_in[15];
    const float* e_D       = (const float*)d_in[16];
    const float* e_lns     = (const float*)d_in[17];
    const float* e_lnb     = (const float*)d_in[18];
    float* out = (float*)d_out;

    float* qkv;
    cudaGetSymbolAddress((void**)&qkv, g_qkv);

    cudaFuncSetAttribute(attn_kernel, cudaFuncAttributeMaxDynamicSharedMemorySize,
                         2 * L * HD * (int)sizeof(float));

    // gating chain
    gemm_plain<<<dim3(3 * DIM / 128, BATCH * L / 128), 256>>>(x, sa_in_w, sa_in_b, qkv, DIM, 3 * DIM);
    attn_kernel<<<dim3(NH, BATCH), 256, 2 * L * HD * sizeof(float)>>>();
    k2_kernel<<<NEXP, 256>>>(eq, ca_in_w, ca_in_b);
    vq_kernel<<<64, 256>>>(ca_in_w, ca_in_b, sa_out_w, sa_out_b);
    scores_kernel<<<BATCH * L / 64, 256>>>();
    aw_kernel<<<BATCH * L, 64>>>();
    gate_kernel<<<BATCH, 256>>>();

    // experts (gated per (e,b) on g_wsel)
    zero_kernel<<<(BATCH * DIM + 255) / 256, 256>>>(out, BATCH * DIM);
    gemm_xz_tf32<<<dim3(2 * DIM / 128, L / 128, EB), 256>>>(x, e_in_w, e_in_b);
    conv_kernel<<<dim3(L, EB), DIM>>>(e_conv_w, e_conv_b);
    dbl_kernel<<<dim3(4, EB), 256>>>(e_xproj_w);
    scan_kernel<<<dim3(4, EB), 192>>>(e_dtw, e_dtb, e_Alog, e_D);
    finalize_kernel<<<EB, 256>>>(e_lns, e_lnb, out);
}

// round 5
// speedup vs baseline: 2.4232x; 1.4561x over previous
#include <cuda_runtime.h>
#include <math.h>
#include <stdint.h>

// ---------------- problem constants ----------------
constexpr int BATCH = 16;
constexpr int L     = 256;      // H*W
constexpr int DIM   = 768;
constexpr int NH    = 8;
constexpr int HD    = 96;
constexpr int NEXP  = 8;
constexpr int EB    = NEXP * BATCH;   // 128 (expert, batch) pairs
constexpr float SCALE = 0.102062072615966f; // 1/sqrt(96)

// ---------------- device scratch (static; no allocation) ----------------
__device__ float g_qkv   [BATCH * L * 3 * DIM];
__device__ float g_ctx   [BATCH * L * DIM];
__device__ float g_k2    [NEXP * DIM];
__device__ float g_u     [64 * DIM];              // u[he] = Wq_h^T k2[e,h]
__device__ float g_qvec  [64 * DIM];
__device__ float g_const [64];
__device__ float g_scores[BATCH * L * 64];
__device__ float g_aw    [BATCH * L * NEXP];
__device__ float g_wsel  [EB];
__device__ float g_xz    [EB * L * 2 * DIM];
__device__ float g_xc    [EB * L * DIM];
__device__ float g_dbl   [EB * 4 * L * 6];
__device__ float g_ydir  [(size_t)EB * 4 * L * DIM];

// ---------------- helpers ----------------
__device__ __forceinline__ float siluf(float x) { return x / (1.f + __expf(-x)); }
__device__ __forceinline__ float softplusf(float x) {
    return (x > 20.f) ? x : __logf(1.f + __expf(x));
}
__device__ __forceinline__ int dirmap(int dir, int t) {
    int tt = (dir & 1) ? (L - 1 - t) : t;
    if (dir < 2) return tt;
    return ((tt & 15) << 4) | (tt >> 4);
}
__device__ __forceinline__ uint32_t f2tf32(float f) {
    uint32_t u;
    asm("cvt.rna.tf32.f32 %0, %1;" : "=r"(u) : "f"(f));
    return u;
}
__device__ __forceinline__ void mma_tf32(float* c, uint32_t a0, uint32_t a1,
                                         uint32_t a2, uint32_t a3,
                                         uint32_t b0, uint32_t b1) {
    asm volatile(
        "mma.sync.aligned.m16n8k8.row.col.f32.tf32.tf32.f32 "
        "{%0,%1,%2,%3}, {%4,%5,%6,%7}, {%8,%9}, {%0,%1,%2,%3};"
        : "+f"(c[0]), "+f"(c[1]), "+f"(c[2]), "+f"(c[3])
        : "r"(a0), "r"(a1), "r"(a2), "r"(a3), "r"(b0), "r"(b1));
}

// ------- tf32 tensor-core 128x128 GEMM tile: C = A @ W^T + bias -------
// A: (M,K) row-major, Wt: (N,K) row-major, K multiple of 16.
__device__ __forceinline__ void gemm128_tf32(const float* __restrict__ A,
                                             const float* __restrict__ Wt,
                                             const float* __restrict__ bias,
                                             float* __restrict__ C,
                                             int K, int ldc) {
    __shared__ uint32_t As[2][128][20];
    __shared__ uint32_t Bs[2][128][20];

    const int tid  = threadIdx.x;
    const int wid  = tid >> 5, lane = tid & 31;
    const int mw   = wid & 1, nw = wid >> 1;
    const int m0   = mw * 64, n0 = nw * 32;
    const int r    = lane >> 2, c4 = lane & 3;
    const int lrow0 = tid >> 2;
    const int lrow1 = lrow0 + 64;
    const int lkc   = (tid & 3) << 2;

    float acc[4][4][4];
#pragma unroll
    for (int i = 0; i < 4; i++)
#pragma unroll
        for (int j = 0; j < 4; j++)
#pragma unroll
            for (int q = 0; q < 4; q++) acc[i][j][q] = 0.f;

    float4 pa0, pa1, pb0, pb1;
    pa0 = *(const float4*)&A [(size_t)lrow0 * K + lkc];
    pa1 = *(const float4*)&A [(size_t)lrow1 * K + lkc];
    pb0 = *(const float4*)&Wt[(size_t)lrow0 * K + lkc];
    pb1 = *(const float4*)&Wt[(size_t)lrow1 * K + lkc];
    As[0][lrow0][lkc + 0] = f2tf32(pa0.x); As[0][lrow0][lkc + 1] = f2tf32(pa0.y);
    As[0][lrow0][lkc + 2] = f2tf32(pa0.z); As[0][lrow0][lkc + 3] = f2tf32(pa0.w);
    As[0][lrow1][lkc + 0] = f2tf32(pa1.x); As[0][lrow1][lkc + 1] = f2tf32(pa1.y);
    As[0][lrow1][lkc + 2] = f2tf32(pa1.z); As[0][lrow1][lkc + 3] = f2tf32(pa1.w);
    Bs[0][lrow0][lkc + 0] = f2tf32(pb0.x); Bs[0][lrow0][lkc + 1] = f2tf32(pb0.y);
    Bs[0][lrow0][lkc + 2] = f2tf32(pb0.z); Bs[0][lrow0][lkc + 3] = f2tf32(pb0.w);
    Bs[0][lrow1][lkc + 0] = f2tf32(pb1.x); Bs[0][lrow1][lkc + 1] = f2tf32(pb1.y);
    Bs[0][lrow1][lkc + 2] = f2tf32(pb1.z); Bs[0][lrow1][lkc + 3] = f2tf32(pb1.w);
    __syncthreads();

    int buf = 0;
    for (int k0 = 16; k0 <= K; k0 += 16) {
        if (k0 < K) {
            pa0 = *(const float4*)&A [(size_t)lrow0 * K + k0 + lkc];
            pa1 = *(const float4*)&A [(size_t)lrow1 * K + k0 + lkc];
            pb0 = *(const float4*)&Wt[(size_t)lrow0 * K + k0 + lkc];
            pb1 = *(const float4*)&Wt[(size_t)lrow1 * K + k0 + lkc];
        }
#pragma unroll
        for (int kk = 0; kk < 16; kk += 8) {
            uint32_t bf0[4], bf1[4];
#pragma unroll
            for (int fn = 0; fn < 4; fn++) {
                bf0[fn] = Bs[buf][n0 + fn * 8 + r][kk + c4];
                bf1[fn] = Bs[buf][n0 + fn * 8 + r][kk + 4 + c4];
            }
#pragma unroll
            for (int fm = 0; fm < 4; fm++) {
                uint32_t a0 = As[buf][m0 + fm * 16 + r    ][kk + c4];
                uint32_t a1 = As[buf][m0 + fm * 16 + r + 8][kk + c4];
                uint32_t a2 = As[buf][m0 + fm * 16 + r    ][kk + 4 + c4];
                uint32_t a3 = As[buf][m0 + fm * 16 + r + 8][kk + 4 + c4];
#pragma unroll
                for (int fn = 0; fn < 4; fn++)
                    mma_tf32(acc[fm][fn], a0, a1, a2, a3, bf0[fn], bf1[fn]);
            }
        }
        if (k0 < K) {
            int nb = buf ^ 1;
            As[nb][lrow0][lkc + 0] = f2tf32(pa0.x); As[nb][lrow0][lkc + 1] = f2tf32(pa0.y);
            As[nb][lrow0][lkc + 2] = f2tf32(pa0.z); As[nb][lrow0][lkc + 3] = f2tf32(pa0.w);
            As[nb][lrow1][lkc + 0] = f2tf32(pa1.x); As[nb][lrow1][lkc + 1] = f2tf32(pa1.y);
            As[nb][lrow1][lkc + 2] = f2tf32(pa1.z); As[nb][lrow1][lkc + 3] = f2tf32(pa1.w);
            Bs[nb][lrow0][lkc + 0] = f2tf32(pb0.x); Bs[nb][lrow0][lkc + 1] = f2tf32(pb0.y);
            Bs[nb][lrow0][lkc + 2] = f2tf32(pb0.z); Bs[nb][lrow0][lkc + 3] = f2tf32(pb0.w);
            Bs[nb][lrow1][lkc + 0] = f2tf32(pb1.x); Bs[nb][lrow1][lkc + 1] = f2tf32(pb1.y);
            Bs[nb][lrow1][lkc + 2] = f2tf32(pb1.z); Bs[nb][lrow1][lkc + 3] = f2tf32(pb1.w);
            __syncthreads();
            buf = nb;
        }
    }

#pragma unroll
    for (int fm = 0; fm < 4; fm++) {
#pragma unroll
        for (int fn = 0; fn < 4; fn++) {
            int rl = m0 + fm * 16 + r;
            int cl = n0 + fn * 8 + (lane & 3) * 2;
            float2 v0, v1;
            v0.x = acc[fm][fn][0] + bias[cl];
            v0.y = acc[fm][fn][1] + bias[cl + 1];
            v1.x = acc[fm][fn][2] + bias[cl];
            v1.y = acc[fm][fn][3] + bias[cl + 1];
            *(float2*)&C[(size_t)rl * ldc + cl]       = v0;
            *(float2*)&C[(size_t)(rl + 8) * ldc + cl] = v1;
        }
    }
}

__global__ void __launch_bounds__(256, 2)
gemm_tf32_plain(const float* __restrict__ A, const float* __restrict__ Wt,
                const float* __restrict__ bias, float* __restrict__ C, int K, int N) {
    gemm128_tf32(A + (size_t)blockIdx.y * 128 * K,
                 Wt + (size_t)blockIdx.x * 128 * K,
                 bias + blockIdx.x * 128,
                 C + (size_t)blockIdx.y * 128 * N + blockIdx.x * 128, K, N);
}

__global__ void __launch_bounds__(256, 2)
gemm_xz_tf32(const float* __restrict__ x, const float* __restrict__ ew,
             const float* __restrict__ eb) {
    int z = blockIdx.z;
    if (g_wsel[z] == 0.f) return;
    int e = z >> 4, b = z & 15;
    gemm128_tf32(x + ((size_t)b * L + blockIdx.y * 128) * DIM,
                 ew + ((size_t)e * 2 * DIM + blockIdx.x * 128) * DIM,
                 eb + e * 2 * DIM + blockIdx.x * 128,
                 g_xz + (size_t)z * L * 2 * DIM
                      + (size_t)blockIdx.y * 128 * 2 * DIM + blockIdx.x * 128,
                 DIM, 2 * DIM);
}

// ---------------- fused self-attention ----------------
__global__ void __launch_bounds__(256) attn_kernel() {
    const int h = blockIdx.x, b = blockIdx.y;
    extern __shared__ float sm[];
    float* Ksh = sm;
    float* Vsh = sm + L * HD;
    const float* base = g_qkv + (size_t)b * L * 3 * DIM;
    const int tid = threadIdx.x;

    for (int i = tid; i < L * HD; i += 256) {
        int m = i / HD, d = i - m * HD;
        Ksh[i] = base[(size_t)m * 3 * DIM + DIM     + h * HD + d];
        Vsh[i] = base[(size_t)m * 3 * DIM + 2 * DIM + h * HD + d];
    }
    __syncthreads();

    float sc[L];
    {
        float rq[HD];
        const float* qp = base + (size_t)tid * 3 * DIM + h * HD;
#pragma unroll
        for (int d = 0; d < HD; d++) rq[d] = qp[d];
        float mx = -1e30f;
        for (int m = 0; m < L; m++) {
            float s = 0.f;
            const float* kp = Ksh + m * HD;
#pragma unroll
            for (int d = 0; d < HD; d++) s += rq[d] * kp[d];
            s *= SCALE;
            sc[m] = s;
            mx = fmaxf(mx, s);
        }
        float sum = 0.f;
        for (int m = 0; m < L; m++) { float e = __expf(sc[m] - mx); sc[m] = e; sum += e; }
        float inv = 1.f / sum;
        for (int m = 0; m < L; m++) sc[m] *= inv;
    }
    {
        float accv[HD];
#pragma unroll
        for (int d = 0; d < HD; d++) accv[d] = 0.f;
        for (int m = 0; m < L; m++) {
            float p = sc[m];
            const float* vp = Vsh + m * HD;
#pragma unroll
            for (int d = 0; d < HD; d++) accv[d] += p * vp[d];
        }
        float* op = g_ctx + ((size_t)b * L + tid) * DIM + h * HD;
#pragma unroll
        for (int d = 0; d < HD; d++) op[d] = accv[d];
    }
}

// ---------------- fused gating projection ----------------
__global__ void k2_kernel(const float* __restrict__ eq, const float* __restrict__ ca_w,
                          const float* __restrict__ ca_b) {
    int e = blockIdx.x;
    int c = blockIdx.y * 256 + threadIdx.x;
    __shared__ float qs[DIM];
    for (int i = threadIdx.x; i < DIM; i += 256) qs[i] = eq[e * DIM + i];
    __syncthreads();
    const float* w = ca_w + (size_t)(DIM + c) * DIM;
    float s = ca_b[DIM + c];
    for (int k = 0; k < DIM; k++) s += qs[k] * w[k];
    g_k2[e * DIM + c] = s;
}

// u[he][c] = sum_d ca_w[(h*HD+d)*DIM + c] * k2[e][h*HD+d]
__global__ void __launch_bounds__(256)
vq1_kernel(const float* __restrict__ ca_w) {
    int he = blockIdx.x;
    int e = he & 7, h = he >> 3;
    int c = blockIdx.y * 256 + threadIdx.x;
    __shared__ float k2s[HD];
    if (threadIdx.x < HD) k2s[threadIdx.x] = g_k2[e * DIM + h * HD + threadIdx.x];
    __syncthreads();
    float s = 0.f;
#pragma unroll 4
    for (int d = 0; d < HD; d++) s += ca_w[(size_t)(h * HD + d) * DIM + c] * k2s[d];
    g_u[(size_t)he * DIM + c] = s;
}

// const[he] = sa_ob . u[he] + ca_b[h*HD..] . k2[e,h]
__global__ void __launch_bounds__(256)
vqc_kernel(const float* __restrict__ ca_b, const float* __restrict__ sa_ob) {
    int he = blockIdx.x;
    int e = he & 7, h = he >> 3;
    int tid = threadIdx.x;
    __shared__ float red[256];
    float part = 0.f;
    for (int c = tid; c < DIM; c += 256) part += sa_ob[c] * g_u[(size_t)he * DIM + c];
    if (tid < HD) part += ca_b[h * HD + tid] * g_k2[e * DIM + h * HD + tid];
    red[tid] = part;
    __syncthreads();
    for (int s = 128; s; s >>= 1) {
        if (tid < s) red[tid] += red[tid + s];
        __syncthreads();
    }
    if (tid == 0) g_const[he] = red[0];
}

// Qvec[64, DIM] = U[64, DIM] @ Wo[DIM, DIM]   (Wo row-major, no transpose)
__global__ void __launch_bounds__(256)
vq2_kernel(const float* __restrict__ sa_ow) {
    __shared__ float Us[16][68];
    __shared__ float Ws[16][68];
    const int tid = threadIdx.x;
    const int tx = tid & 15, ty = tid >> 4;
    const int n0 = blockIdx.x * 64;
    const int row = tid >> 2, kc = (tid & 3) << 2;

    float acc[4][4];
#pragma unroll
    for (int i = 0; i < 4; i++)
#pragma unroll
        for (int j = 0; j < 4; j++) acc[i][j] = 0.f;

    for (int k0 = 0; k0 < DIM; k0 += 16) {
        float4 vu = *(const float4*)&g_u[(size_t)row * DIM + k0 + kc];
        Us[kc + 0][row] = vu.x; Us[kc + 1][row] = vu.y;
        Us[kc + 2][row] = vu.z; Us[kc + 3][row] = vu.w;
        // Ws[k][col]: 16 rows of Wo, 64 cols; 256 threads -> each loads 4
        int wk = tid >> 4, wc = (tid & 15) * 4;
        float4 vw = *(const float4*)&sa_ow[(size_t)(k0 + wk) * DIM + n0 + wc];
        Ws[wk][wc + 0] = vw.x; Ws[wk][wc + 1] = vw.y;
        Ws[wk][wc + 2] = vw.z; Ws[wk][wc + 3] = vw.w;
        __syncthreads();
#pragma unroll
        for (int k = 0; k < 16; k++) {
            float a[4], w[4];
            *(float4*)&a[0] = *(const float4*)&Us[k][ty * 4];
            *(float4*)&w[0] = *(const float4*)&Ws[k][tx * 4];
#pragma unroll
            for (int i = 0; i < 4; i++)
#pragma unroll
                for (int j = 0; j < 4; j++) acc[i][j] += a[i] * w[j];
        }
        __syncthreads();
    }
#pragma unroll
    for (int i = 0; i < 4; i++)
#pragma unroll
        for (int j = 0; j < 4; j++)
            g_qvec[(size_t)(ty * 4 + i) * DIM + n0 + tx * 4 + j] = acc[i][j];
}

// scores[bl, he] = ctx[bl] . Qvec[he]
__global__ void __launch_bounds__(256)
scores_kernel() {
    __shared__ float As[16][68];
    __shared__ float Qs[16][68];
    const int tid = threadIdx.x;
    const int tx = tid & 15, ty = tid >> 4;
    const int row = tid >> 2, kc = (tid & 3) << 2;
    const float* A = g_ctx + (size_t)blockIdx.x * 64 * DIM;

    float acc[4][4];
#pragma unroll
    for (int i = 0; i < 4; i++)
#pragma unroll
        for (int j = 0; j < 4; j++) acc[i][j] = 0.f;

    for (int k0 = 0; k0 < DIM; k0 += 16) {
        float4 va = *(const float4*)&A[(size_t)row * DIM + k0 + kc];
        float4 vq = *(const float4*)&g_qvec[(size_t)row * DIM + k0 + kc];
        As[kc + 0][row] = va.x; As[kc + 1][row] = va.y;
        As[kc + 2][row] = va.z; As[kc + 3][row] = va.w;
        Qs[kc + 0][row] = vq.x; Qs[kc + 1][row] = vq.y;
        Qs[kc + 2][row] = vq.z; Qs[kc + 3][row] = vq.w;
        __syncthreads();
#pragma unroll
        for (int k = 0; k < 16; k++) {
            float a[4], q[4];
            *(float4*)&a[0] = *(const float4*)&As[k][ty * 4];
            *(float4*)&q[0] = *(const float4*)&Qs[k][tx * 4];
#pragma unroll
            for (int i = 0; i < 4; i++)
#pragma unroll
                for (int j = 0; j < 4; j++) acc[i][j] += a[i] * q[j];
        }
        __syncthreads();
    }
#pragma unroll
    for (int i = 0; i < 4; i++)
#pragma unroll
        for (int j = 0; j < 4; j++)
            g_scores[((size_t)blockIdx.x * 64 + ty * 4 + i) * 64 + tx * 4 + j] = acc[i][j];
}

__global__ void aw_kernel() {
    int bl = blockIdx.x;
    int tid = threadIdx.x;        // he = h*8+e
    float s = (g_scores[(size_t)bl * 64 + tid] + g_const[tid]) * SCALE;
    float m = s;
#pragma unroll
    for (int o = 4; o; o >>= 1) m = fmaxf(m, __shfl_xor_sync(0xffffffffu, m, o, 8));
    float ex = __expf(s - m);
    float sum = ex;
#pragma unroll
    for (int o = 4; o; o >>= 1) sum += __shfl_xor_sync(0xffffffffu, sum, o, 8);
    float p = ex / sum;
    __shared__ float sh[64];
    sh[tid] = p;
    __syncthreads();
    if (tid < 8) {
        float a = 0.f;
        for (int hh = 0; hh < 8; hh++) a += sh[hh * 8 + tid];
        g_aw[(size_t)bl * 8 + tid] = a * 0.125f;
    }
}

__global__ void gate_kernel() {
    int b = blockIdx.x;
    __shared__ float s[8];
    if (threadIdx.x < 8) s[threadIdx.x] = 0.f;
    __syncthreads();
    const float* p = g_aw + ((size_t)b * L + threadIdx.x) * 8;
    for (int e = 0; e < 8; e++) atomicAdd(&s[e], p[e]);
    __syncthreads();
    if (threadIdx.x == 0) {
        float g[8];
        float mx = -1e30f;
        for (int e = 0; e < 8; e++) { g[e] = s[e] * (1.f / 256.f); mx = fmaxf(mx, g[e]); }
        float sum = 0.f;
        for (int e = 0; e < 8; e++) { g[e] = __expf(g[e] - mx); sum += g[e]; }
        for (int e = 0; e < 8; e++) g[e] /= sum;
        int i0 = 0;
        for (int e = 1; e < 8; e++) if (g[e] > g[i0]) i0 = e;
        int i1 = -1;
        for (int e = 0; e < 8; e++) if (e != i0 && (i1 < 0 || g[e] > g[i1])) i1 = e;
        float mm = fmaxf(g[i0], g[i1]);
        float e0 = __expf(g[i0] - mm), e1 = __expf(g[i1] - mm);
        for (int e = 0; e < 8; e++) g_wsel[e * BATCH + b] = 0.f;
        g_wsel[i0 * BATCH + b] = e0 / (e0 + e1);
        g_wsel[i1 * BATCH + b] = e1 / (e0 + e1);
    }
}

// ---------------- expert: depthwise conv 3x3 + bias + silu ----------------
__global__ void conv_kernel(const float* __restrict__ cw, const float* __restrict__ cb) {
    int z = blockIdx.y;
    if (g_wsel[z] == 0.f) return;
    int e = z >> 4;
    int pix = blockIdx.x;
    int py = pix >> 4, px = pix & 15;
    int c = threadIdx.x;
    const float* w = cw + ((size_t)e * DIM + c) * 9;
    const float* in = g_xz + (size_t)z * L * 2 * DIM;
    float acc = cb[e * DIM + c];
#pragma unroll
    for (int dy = -1; dy <= 1; dy++) {
        int y = py + dy;
        if ((unsigned)y >= 16u) continue;
#pragma unroll
        for (int dx = -1; dx <= 1; dx++) {
            int xw = px + dx;
            if ((unsigned)xw >= 16u) continue;
            acc += in[(size_t)(y * 16 + xw) * 2 * DIM + c] * w[(dy + 1) * 3 + (dx + 1)];
        }
    }
    g_xc[(size_t)z * L * DIM + (size_t)pix * DIM + c] = siluf(acc);
}

// ---------------- expert: per-direction (dt_lin,B,C) projections ----------------
__global__ void dbl_kernel(const float* __restrict__ xproj) {
    int z = blockIdx.y;
    if (g_wsel[z] == 0.f) return;
    int e = z >> 4;
    int dir = blockIdx.x;
    __shared__ float wsh[6 * DIM];
    const float* wp = xproj + (size_t)(e * 4 + dir) * 6 * DIM;
    for (int i = threadIdx.x; i < 6 * DIM; i += 256) wsh[i] = wp[i];
    __syncthreads();
    int warp = threadIdx.x >> 5, lane = threadIdx.x & 31;
    const float* xcb = g_xc + (size_t)z * L * DIM;
    for (int t = warp; t < L; t += 8) {
        int l = dirmap(dir, t);
        const float* row = xcb + (size_t)l * DIM;
        float a0 = 0, a1 = 0, a2 = 0, a3 = 0, a4 = 0, a5 = 0;
        for (int d = lane; d < DIM; d += 32) {
            float xv = row[d];
            a0 += xv * wsh[d];
            a1 += xv * wsh[DIM + d];
            a2 += xv * wsh[2 * DIM + d];
            a3 += xv * wsh[3 * DIM + d];
            a4 += xv * wsh[4 * DIM + d];
            a5 += xv * wsh[5 * DIM + d];
        }
#pragma unroll
        for (int o = 16; o; o >>= 1) {
            a0 += __shfl_xor_sync(0xffffffffu, a0, o);
            a1 += __shfl_xor_sync(0xffffffffu, a1, o);
            a2 += __shfl_xor_sync(0xffffffffu, a2, o);
            a3 += __shfl_xor_sync(0xffffffffu, a3, o);
            a4 += __shfl_xor_sync(0xffffffffu, a4, o);
            a5 += __shfl_xor_sync(0xffffffffu, a5, o);
        }
        if (lane == 0) {
            float* outp = g_dbl + ((size_t)(z * 4 + dir) * L + t) * 6;
            outp[0] = a0; outp[1] = a1; outp[2] = a2;
            outp[3] = a3; outp[4] = a4; outp[5] = a5;
        }
    }
}

// ---------------- expert: selective scan, one block per (chunk, dir, z) ----------
__global__ void __launch_bounds__(192)
scan_kernel(const float* __restrict__ dtw, const float* __restrict__ dtb,
            const float* __restrict__ Alog, const float* __restrict__ Dp) {
    int z = blockIdx.z;
    if (g_wsel[z] == 0.f) return;
    int e = z >> 4;
    int dir = blockIdx.y;
    int d = blockIdx.x * 192 + threadIdx.x;
    __shared__ float dsh[L * 6];
    const float* xcb = g_xc + (size_t)z * L * DIM;

    const float* db = g_dbl + (size_t)(z * 4 + dir) * L * 6;
    for (int i = threadIdx.x; i < L * 6; i += 192) dsh[i] = db[i];
    __syncthreads();

    int pb = (e * 4 + dir) * DIM + d;
    float w0 = dtw[(size_t)pb * 4 + 0], w1 = dtw[(size_t)pb * 4 + 1];
    float w2 = dtw[(size_t)pb * 4 + 2], w3 = dtw[(size_t)pb * 4 + 3];
    float bb = dtb[pb];
    float A  = -__expf(Alog[pb]);
    float Dv = Dp[pb];
    float hst = 0.f;
    float* yp = g_ydir + (size_t)(z * 4 + dir) * L * DIM + d;
    for (int t = 0; t < L; t++) {
        const float* dr = dsh + t * 6;
        float dtl = dr[0] * w0 + dr[1] * w1 + dr[2] * w2 + dr[3] * w3 + bb;
        float dt = softplusf(dtl);
        int l = dirmap(dir, t);
        float xv = xcb[(size_t)l * DIM + d];
        hst = __expf(dt * A) * hst + (dt * xv) * dr[4];
        yp[(size_t)t * DIM] = hst * dr[5] + Dv * xv;
    }
}

// ------- expert finalize: two-phase LN -------
__global__ void __launch_bounds__(256)
finalize_kernel(const float* __restrict__ lns, const float* __restrict__ lnb,
                float* __restrict__ out) {
    int z = blockIdx.x;
    float wgt = g_wsel[z];
    if (wgt == 0.f) return;
    int e = z >> 4, b = z & 15;
    int tid = threadIdx.x;
    int wid = tid >> 5, lane = tid & 31;
    __shared__ float smu[L], srs[L];

    const float* y0b = g_ydir + (size_t)(z * 4 + 0) * L * DIM;
    const float* y1b = g_ydir + (size_t)(z * 4 + 1) * L * DIM;
    const float* y2b = g_ydir + (size_t)(z * 4 + 2) * L * DIM;
    const float* y3b = g_ydir + (size_t)(z * 4 + 3) * L * DIM;
    const float* zb = g_xz + (size_t)z * L * 2 * DIM + DIM;

    for (int l = wid; l < L; l += 8) {
        int lt = ((l & 15) << 4) | (l >> 4);
        const float* p0 = y0b + (size_t)l * DIM;
        const float* p1 = y1b + (size_t)(L - 1 - l) * DIM;
        const float* p2 = y2b + (size_t)lt * DIM;
        const float* p3 = y3b + (size_t)(L - 1 - lt) * DIM;
        float s = 0.f, ss = 0.f;
        for (int d = lane; d < DIM; d += 32) {
            float v = p0[d] + p1[d] + p2[d] + p3[d];
            s += v; ss += v * v;
        }
#pragma unroll
        for (int o = 16; o; o >>= 1) {
            s  += __shfl_xor_sync(0xffffffffu, s, o);
            ss += __shfl_xor_sync(0xffffffffu, ss, o);
        }
        if (lane == 0) {
            float mu = s * (1.f / 768.f);
            float var = ss * (1.f / 768.f) - mu * mu;
            smu[l] = mu;
            srs[l] = rsqrtf(var + 1e-5f);
        }
    }
    __syncthreads();

    float s0 = lns[e * DIM + tid], s1 = lns[e * DIM + tid + 256], s2 = lns[e * DIM + tid + 512];
    float b0 = lnb[e * DIM + tid], b1 = lnb[e * DIM + tid + 256], b2 = lnb[e * DIM + tid + 512];
    float a0 = 0.f, a1 = 0.f, a2 = 0.f;

    for (int l = 0; l < L; l++) {
        int lt = ((l & 15) << 4) | (l >> 4);
        size_t r0 = (size_t)l * DIM;
        size_t r1 = (size_t)(L - 1 - l) * DIM;
        size_t r2 = (size_t)lt * DIM;
        size_t r3 = (size_t)(L - 1 - lt) * DIM;
        float y0 = y0b[r0 + tid]       + y1b[r1 + tid]       + y2b[r2 + tid]       + y3b[r3 + tid];
        float y1 = y0b[r0 + tid + 256] + y1b[r1 + tid + 256] + y2b[r2 + tid + 256] + y3b[r3 + tid + 256];
        float y2 = y0b[r0 + tid + 512] + y1b[r1 + tid + 512] + y2b[r2 + tid + 512] + y3b[r3 + tid + 512];
        float mu = smu[l], rstd = srs[l];

        float z0 = zb[(size_t)l * 2 * DIM + tid];
        float z1 = zb[(size_t)l * 2 * DIM + tid + 256];
        float z2 = zb[(size_t)l * 2 * DIM + tid + 512];
        a0 += ((y0 - mu) * rstd * s0 + b0) * siluf(z0);
        a1 += ((y1 - mu) * rstd * s1 + b1) * siluf(z1);
        a2 += ((y2 - mu) * rstd * s2 + b2) * siluf(z2);
    }
    float sc = wgt * (1.f / 256.f);
    atomicAdd(&out[b * DIM + tid],       a0 * sc);
    atomicAdd(&out[b * DIM + tid + 256], a1 * sc);
    atomicAdd(&out[b * DIM + tid + 512], a2 * sc);
}

__global__ void zero_kernel(float* __restrict__ out, int n) {
    int i = blockIdx.x * blockDim.x + threadIdx.x;
    if (i < n) out[i] = 0.f;
}

// ---------------- host launcher ----------------
extern "C" void kernel_launch(void* const* d_in, const int* in_sizes, int n_in,
                              void* d_out, int out_size) {
    const float* x         = (const float*)d_in[0];
    const float* sa_in_w   = (const float*)d_in[1];
    const float* sa_in_b   = (const float*)d_in[2];
    const float* sa_out_w  = (const float*)d_in[3];
    const float* sa_out_b  = (const float*)d_in[4];
    const float* ca_in_w   = (const float*)d_in[5];
    const float* ca_in_b   = (const float*)d_in[6];
    const float* eq        = (const float*)d_in[7];
    const float* e_in_w    = (const float*)d_in[8];
    const float* e_in_b    = (const float*)d_in[9];
    const float* e_conv_w  = (const float*)d_in[10];
    const float* e_conv_b  = (const float*)d_in[11];
    const float* e_xproj_w = (const float*)d_in[12];
    const float* e_dtw     = (const float*)d_in[13];
    const float* e_dtb     = (const float*)d_in[14];
    const float* e_Alog    = (const float*)d_in[15];
    const float* e_D       = (const float*)d_in[16];
    const float* e_lns     = (const float*)d_in[17];
    const float* e_lnb     = (const float*)d_in[18];
    float* out = (float*)d_out;

    float* qkv;
    cudaGetSymbolAddress((void**)&qkv, g_qkv);

    cudaFuncSetAttribute(attn_kernel, cudaFuncAttributeMaxDynamicSharedMemorySize,
                         2 * L * HD * (int)sizeof(float));

    // gating chain
    gemm_tf32_plain<<<dim3(3 * DIM / 128, BATCH * L / 128), 256>>>(x, sa_in_w, sa_in_b, qkv, DIM, 3 * DIM);
    attn_kernel<<<dim3(NH, BATCH), 256, 2 * L * HD * sizeof(float)>>>();
    k2_kernel<<<dim3(NEXP, 3), 256>>>(eq, ca_in_w, ca_in_b);
    vq1_kernel<<<dim3(64, 3), 256>>>(ca_in_w);
    vqc_kernel<<<64, 256>>>(ca_in_b, sa_out_b);
    vq2_kernel<<<DIM / 64, 256>>>(sa_out_w);
    scores_kernel<<<BATCH * L / 64, 256>>>();
    aw_kernel<<<BATCH * L, 64>>>();
    gate_kernel<<<BATCH, 256>>>();

    // experts (gated per (e,b) on g_wsel)
    zero_kernel<<<(BATCH * DIM + 255) / 256, 256>>>(out, BATCH * DIM);
    gemm_xz_tf32<<<dim3(2 * DIM / 128, L / 128, EB), 256>>>(x, e_in_w, e_in_b);
    conv_kernel<<<dim3(L, EB), DIM>>>(e_conv_w, e_conv_b);
    dbl_kernel<<<dim3(4, EB), 256>>>(e_xproj_w);
    scan_kernel<<<dim3(4, 4, EB), 192>>>(e_dtw, e_dtb, e_Alog, e_D);
    finalize_kernel<<<EB, 256>>>(e_lns, e_lnb, out);
}